// round 2
// baseline (speedup 1.0000x reference)
#include <cuda_runtime.h>
#include <math.h>

// Problem constants (from reference): N=100000, E=1600000, G=1024, D=32, C=10
#define DD 32
#define CC 10
#define MAX_N 100352
#define MAX_G 2048

// Scratch (alloc-free rule: __device__ globals)
__device__ float g_bufH[MAX_N * DD];   // node features between layers
__device__ float g_bufK[MAX_N * DD];   // k / beta
__device__ float g_bufQ[MAX_N * DD];   // q / xl
__device__ float g_bufV[MAX_N * DD];   // v / gamma
__device__ float g_bufS[MAX_N * DD];   // skip path
__device__ float g_bufA[MAX_N * DD];   // aggregation target
__device__ float g_deg[MAX_N];         // in-degree (float)
__device__ float g_gsum[MAX_G * DD];   // graph pooling sums
__device__ float g_gcnt[MAX_G];        // graph node counts

// ---------------------------------------------------------------------------
// Layer 1 node transform (F_IN = 1): k/q/v/skip are scalar*vec + bias
// thread t -> node i = t>>5, feature d = t&31
__global__ __launch_bounds__(256) void node1_kernel(
    const float* __restrict__ x, int N,
    const float* __restrict__ Wk, const float* __restrict__ bk,
    const float* __restrict__ Wq, const float* __restrict__ bq,
    const float* __restrict__ Wv, const float* __restrict__ bv,
    const float* __restrict__ Ws, const float* __restrict__ b)
{
    int t = blockIdx.x * blockDim.x + threadIdx.x;
    if (t >= N * DD) return;
    int i = t >> 5;
    int d = t & 31;
    float xv = __ldg(&x[i]);
    g_bufK[t] = fmaf(xv, __ldg(&Wk[d]), __ldg(&bk[d]));
    g_bufQ[t] = fmaf(xv, __ldg(&Wq[d]), __ldg(&bq[d]));
    g_bufV[t] = fmaf(xv, __ldg(&Wv[d]), __ldg(&bv[d]));
    g_bufS[t] = fmaf(xv, __ldg(&Ws[d]), __ldg(&b[d]));
}

// ---------------------------------------------------------------------------
// ResGated edge pass: agg[dst] += sigmoid(k[dst]+q[src]) * v[src]
// one warp per edge, one lane per feature
__global__ __launch_bounds__(256) void edge_resgated_kernel(
    const int* __restrict__ ei, int E, int count_deg)
{
    int gt = blockIdx.x * blockDim.x + threadIdx.x;
    int e = gt >> 5;
    if (e >= E) return;
    int lane = gt & 31;
    int s = __ldg(&ei[e]);
    int d = __ldg(&ei[E + e]);
    float kk = g_bufK[d * DD + lane];
    float qq = g_bufQ[s * DD + lane];
    float vv = g_bufV[s * DD + lane];
    float gate = __frcp_rn(1.0f + __expf(-(kk + qq)));
    atomicAdd(&g_bufA[d * DD + lane], gate * vv);
    if (count_deg && lane == 0) atomicAdd(&g_deg[d], 1.0f);
}

// ---------------------------------------------------------------------------
// h = relu(agg + skip)
__global__ __launch_bounds__(256) void combine_relu_kernel(int NT)
{
    int t = blockIdx.x * blockDim.x + threadIdx.x;
    if (t >= NT) return;
    g_bufH[t] = fmaxf(g_bufA[t] + g_bufS[t], 0.0f);
}

// ---------------------------------------------------------------------------
// FiLM node transform: xl = h@Wlin ; [beta|gamma] = h@Wfilm + bfilm ;
// skip = relu(gamma_s * (h@Wls) + beta_s), [beta_s|gamma_s] = h@Wfs
// warp per node; h[j] broadcast via shfl feeds 6 FMAs
__global__ __launch_bounds__(256) void film_node_kernel(
    int N,
    const float* __restrict__ Wlin, const float* __restrict__ Wfilm,
    const float* __restrict__ bfilm,
    const float* __restrict__ Wls, const float* __restrict__ Wfs)
{
    __shared__ float sWlin[DD * DD];
    __shared__ float sWfilm[DD * 2 * DD];
    __shared__ float sbf[2 * DD];
    __shared__ float sWls[DD * DD];
    __shared__ float sWfs[DD * 2 * DD];
    for (int j = threadIdx.x; j < DD * DD; j += blockDim.x) {
        sWlin[j] = Wlin[j];
        sWls[j]  = Wls[j];
    }
    for (int j = threadIdx.x; j < DD * 2 * DD; j += blockDim.x) {
        sWfilm[j] = Wfilm[j];
        sWfs[j]   = Wfs[j];
    }
    if (threadIdx.x < 2 * DD) sbf[threadIdx.x] = bfilm[threadIdx.x];
    __syncthreads();

    int gt = blockIdx.x * blockDim.x + threadIdx.x;
    int i = gt >> 5;
    if (i >= N) return;
    int d = gt & 31;
    float h = g_bufH[i * DD + d];
    float xl = 0.0f, be = sbf[d], ga = sbf[DD + d];
    float ls = 0.0f, bs = 0.0f, gs = 0.0f;
#pragma unroll
    for (int j = 0; j < DD; j++) {
        float hj = __shfl_sync(0xffffffffu, h, j);
        xl = fmaf(hj, sWlin[j * DD + d], xl);
        be = fmaf(hj, sWfilm[j * 2 * DD + d], be);
        ga = fmaf(hj, sWfilm[j * 2 * DD + DD + d], ga);
        ls = fmaf(hj, sWls[j * DD + d], ls);
        bs = fmaf(hj, sWfs[j * 2 * DD + d], bs);
        gs = fmaf(hj, sWfs[j * 2 * DD + DD + d], gs);
    }
    int t = i * DD + d;
    g_bufQ[t] = xl;                               // xl
    g_bufK[t] = be;                               // beta
    g_bufV[t] = ga;                               // gamma
    g_bufS[t] = fmaxf(fmaf(gs, ls, bs), 0.0f);    // skip path (already relu'd)
}

// ---------------------------------------------------------------------------
// FiLM edge pass: agg[dst] += relu(gamma[dst]*xl[src] + beta[dst])
__global__ __launch_bounds__(256) void edge_film_kernel(
    const int* __restrict__ ei, int E)
{
    int gt = blockIdx.x * blockDim.x + threadIdx.x;
    int e = gt >> 5;
    if (e >= E) return;
    int lane = gt & 31;
    int s = __ldg(&ei[e]);
    int d = __ldg(&ei[E + e]);
    float ga = g_bufV[d * DD + lane];
    float xl = g_bufQ[s * DD + lane];
    float be = g_bufK[d * DD + lane];
    float msg = fmaxf(fmaf(ga, xl, be), 0.0f);
    atomicAdd(&g_bufA[d * DD + lane], msg);
}

// ---------------------------------------------------------------------------
// FiLM combine + outer relu: h = relu(skip + sums/max(deg,1))
__global__ __launch_bounds__(256) void film_combine_kernel(int NT)
{
    int t = blockIdx.x * blockDim.x + threadIdx.x;
    if (t >= NT) return;
    int i = t >> 5;
    float inv = __frcp_rn(fmaxf(g_deg[i], 1.0f));
    g_bufH[t] = fmaxf(fmaf(g_bufA[t], inv, g_bufS[t]), 0.0f);
}

// ---------------------------------------------------------------------------
// Layer 3 node transform: k/q/v/skip = h @ W + b ; warp per node
__global__ __launch_bounds__(256) void node3_kernel(
    int N,
    const float* __restrict__ Wk, const float* __restrict__ bk,
    const float* __restrict__ Wq, const float* __restrict__ bq,
    const float* __restrict__ Wv, const float* __restrict__ bv,
    const float* __restrict__ Ws, const float* __restrict__ b)
{
    __shared__ float sWk[DD * DD];
    __shared__ float sWq[DD * DD];
    __shared__ float sWv[DD * DD];
    __shared__ float sWs[DD * DD];
    for (int j = threadIdx.x; j < DD * DD; j += blockDim.x) {
        sWk[j] = Wk[j];
        sWq[j] = Wq[j];
        sWv[j] = Wv[j];
        sWs[j] = Ws[j];
    }
    __syncthreads();

    int gt = blockIdx.x * blockDim.x + threadIdx.x;
    int i = gt >> 5;
    if (i >= N) return;
    int d = gt & 31;
    float h = g_bufH[i * DD + d];
    float k = __ldg(&bk[d]);
    float q = __ldg(&bq[d]);
    float v = __ldg(&bv[d]);
    float sk = __ldg(&b[d]);
#pragma unroll
    for (int j = 0; j < DD; j++) {
        float hj = __shfl_sync(0xffffffffu, h, j);
        k  = fmaf(hj, sWk[j * DD + d], k);
        q  = fmaf(hj, sWq[j * DD + d], q);
        v  = fmaf(hj, sWv[j * DD + d], v);
        sk = fmaf(hj, sWs[j * DD + d], sk);
    }
    int t = i * DD + d;
    g_bufK[t] = k;
    g_bufQ[t] = q;
    g_bufV[t] = v;
    g_bufS[t] = sk;
}

// ---------------------------------------------------------------------------
// Pool: h3 = agg + skip (no relu); gsum[batch[i]] += h3[i], gcnt += 1
__global__ __launch_bounds__(256) void pool_kernel(
    const int* __restrict__ batch, int N)
{
    int gt = blockIdx.x * blockDim.x + threadIdx.x;
    int i = gt >> 5;
    if (i >= N) return;
    int lane = gt & 31;
    int t = i * DD + lane;
    float val = g_bufA[t] + g_bufS[t];
    int bgr = __ldg(&batch[i]);
    atomicAdd(&g_gsum[bgr * DD + lane], val);
    if (lane == 0) atomicAdd(&g_gcnt[bgr], 1.0f);
}

// ---------------------------------------------------------------------------
// Final: out[g] = (gsum[g]/max(cnt,1)) @ lin_W + lin_b   [G x 10]
__global__ __launch_bounds__(128) void final_kernel(
    const float* __restrict__ linW, const float* __restrict__ linb,
    float* __restrict__ out, int G)
{
    __shared__ float sW[DD * CC];
    __shared__ float sb[CC];
    for (int j = threadIdx.x; j < DD * CC; j += blockDim.x) sW[j] = linW[j];
    if (threadIdx.x < CC) sb[threadIdx.x] = linb[threadIdx.x];
    __syncthreads();

    int g = blockIdx.x * blockDim.x + threadIdx.x;
    if (g >= G) return;
    float inv = __frcp_rn(fmaxf(g_gcnt[g], 1.0f));
    float acc[CC];
#pragma unroll
    for (int c = 0; c < CC; c++) acc[c] = sb[c];
#pragma unroll
    for (int j = 0; j < DD; j++) {
        float m = g_gsum[g * DD + j] * inv;
#pragma unroll
        for (int c = 0; c < CC; c++) acc[c] = fmaf(m, sW[j * CC + c], acc[c]);
    }
#pragma unroll
    for (int c = 0; c < CC; c++) out[g * CC + c] = acc[c];
}

// ---------------------------------------------------------------------------
static inline int nblk(long long threads, int tpb) {
    return (int)((threads + tpb - 1) / tpb);
}

extern "C" void kernel_launch(void* const* d_in, const int* in_sizes, int n_in,
                              void* d_out, int out_size)
{
    // metadata order:
    // 0 x | 1 edge_index | 2 batch | 3 num_graphs |
    // 4..11 c1: Wk bk Wq bq Wv bv Wskip b |
    // 12..16 c2: Wlin Wfilm bfilm Wls Wfs |
    // 17..24 c3: Wk bk Wq bq Wv bv Wskip b |
    // 25 lin_W | 26 lin_b
    const float* x     = (const float*)d_in[0];
    const int*   ei    = (const int*)d_in[1];
    const int*   batch = (const int*)d_in[2];
    const float* c1_Wk = (const float*)d_in[4];
    const float* c1_bk = (const float*)d_in[5];
    const float* c1_Wq = (const float*)d_in[6];
    const float* c1_bq = (const float*)d_in[7];
    const float* c1_Wv = (const float*)d_in[8];
    const float* c1_bv = (const float*)d_in[9];
    const float* c1_Ws = (const float*)d_in[10];
    const float* c1_b  = (const float*)d_in[11];
    const float* c2_Wlin  = (const float*)d_in[12];
    const float* c2_Wfilm = (const float*)d_in[13];
    const float* c2_bfilm = (const float*)d_in[14];
    const float* c2_Wls   = (const float*)d_in[15];
    const float* c2_Wfs   = (const float*)d_in[16];
    const float* c3_Wk = (const float*)d_in[17];
    const float* c3_bk = (const float*)d_in[18];
    const float* c3_Wq = (const float*)d_in[19];
    const float* c3_bq = (const float*)d_in[20];
    const float* c3_Wv = (const float*)d_in[21];
    const float* c3_bv = (const float*)d_in[22];
    const float* c3_Ws = (const float*)d_in[23];
    const float* c3_b  = (const float*)d_in[24];
    const float* linW  = (const float*)d_in[25];
    const float* linb  = (const float*)d_in[26];
    float* out = (float*)d_out;

    int N = in_sizes[0];          // F_IN = 1
    int E = in_sizes[1] / 2;
    int G = out_size / CC;

    void *pA, *pDeg, *pGs, *pGc;
    cudaGetSymbolAddress(&pA,   g_bufA);
    cudaGetSymbolAddress(&pDeg, g_deg);
    cudaGetSymbolAddress(&pGs,  g_gsum);
    cudaGetSymbolAddress(&pGc,  g_gcnt);

    const int TPB = 256;
    long long NT = (long long)N * DD;
    long long ET = (long long)E * 32;

    // ---- Layer 1: ResGated(1 -> 32) ----
    node1_kernel<<<nblk(NT, TPB), TPB>>>(x, N, c1_Wk, c1_bk, c1_Wq, c1_bq,
                                         c1_Wv, c1_bv, c1_Ws, c1_b);
    cudaMemsetAsync(pA, 0, (size_t)NT * sizeof(float));
    cudaMemsetAsync(pDeg, 0, (size_t)N * sizeof(float));
    edge_resgated_kernel<<<nblk(ET, TPB), TPB>>>(ei, E, 1);
    combine_relu_kernel<<<nblk(NT, TPB), TPB>>>((int)NT);

    // ---- Layer 2: FiLM(32 -> 32) ----
    film_node_kernel<<<nblk(NT, TPB), TPB>>>(N, c2_Wlin, c2_Wfilm, c2_bfilm,
                                             c2_Wls, c2_Wfs);
    cudaMemsetAsync(pA, 0, (size_t)NT * sizeof(float));
    edge_film_kernel<<<nblk(ET, TPB), TPB>>>(ei, E);
    film_combine_kernel<<<nblk(NT, TPB), TPB>>>((int)NT);

    // ---- Layer 3: ResGated(32 -> 32), no final relu ----
    node3_kernel<<<nblk(NT, TPB), TPB>>>(N, c3_Wk, c3_bk, c3_Wq, c3_bq,
                                         c3_Wv, c3_bv, c3_Ws, c3_b);
    cudaMemsetAsync(pA, 0, (size_t)NT * sizeof(float));
    edge_resgated_kernel<<<nblk(ET, TPB), TPB>>>(ei, E, 0);

    // ---- Global mean pool + classifier ----
    cudaMemsetAsync(pGs, 0, (size_t)G * DD * sizeof(float));
    cudaMemsetAsync(pGc, 0, (size_t)G * sizeof(float));
    pool_kernel<<<nblk(NT, TPB), TPB>>>(batch, N);
    final_kernel<<<nblk(G, 128), 128>>>(linW, linb, out, G);
}

// round 6
// speedup vs baseline: 1.7132x; 1.7132x over previous
#include <cuda_runtime.h>
#include <math.h>

// Problem constants: N=100000, E=1600000, G=1024, D=32, C=10
#define DD 32
#define CC 10
#define MAX_N 100352
#define MAX_G 2048
#define WSTRIDE 36   // padded smem row stride (floats): 16B-aligned, conflict-free

// Scratch (alloc-free rule: __device__ globals)
__device__ float g_bufH[MAX_N * DD];
__device__ float g_bufK[MAX_N * DD];
__device__ float g_bufQ[MAX_N * DD];
__device__ float g_bufV[MAX_N * DD];
__device__ float g_bufS[MAX_N * DD];
__device__ float g_bufA[MAX_N * DD];
__device__ float g_deg[MAX_N];
__device__ float g_gsum[MAX_G * DD];
__device__ float g_gcnt[MAX_G];

__device__ __forceinline__ void red_add_v4(float* addr, float4 v) {
    asm volatile("red.global.add.v4.f32 [%0], {%1,%2,%3,%4};"
                 :: "l"(addr), "f"(v.x), "f"(v.y), "f"(v.z), "f"(v.w)
                 : "memory");
}

__device__ __forceinline__ float sigmoidf_fast(float x) {
    return __frcp_rn(1.0f + __expf(-x));
}

// ---------------------------------------------------------------------------
// Layer 1 node transform (F_IN = 1)
__global__ __launch_bounds__(256) void node1_kernel(
    const float* __restrict__ x, int N,
    const float* __restrict__ Wk, const float* __restrict__ bk,
    const float* __restrict__ Wq, const float* __restrict__ bq,
    const float* __restrict__ Wv, const float* __restrict__ bv,
    const float* __restrict__ Ws, const float* __restrict__ b)
{
    int t = blockIdx.x * blockDim.x + threadIdx.x;
    if (t >= N * DD) return;
    int i = t >> 5;
    int d = t & 31;
    float xv = __ldg(&x[i]);
    g_bufK[t] = fmaf(xv, __ldg(&Wk[d]), __ldg(&bk[d]));
    g_bufQ[t] = fmaf(xv, __ldg(&Wq[d]), __ldg(&bq[d]));
    g_bufV[t] = fmaf(xv, __ldg(&Wv[d]), __ldg(&bv[d]));
    g_bufS[t] = fmaf(xv, __ldg(&Ws[d]), __ldg(&b[d]));
}

// ---------------------------------------------------------------------------
// ResGated edge pass, 8 lanes per edge, float4 + vector red
__global__ __launch_bounds__(256) void edge_resgated_kernel(
    const int* __restrict__ ei, int E, int count_deg)
{
    int gt = blockIdx.x * blockDim.x + threadIdx.x;
    int e = gt >> 3;
    if (e >= E) return;
    int c = (gt & 7) << 2;          // feature base 0,4,...,28
    int s = __ldg(&ei[e]);
    int d = __ldg(&ei[E + e]);
    float4 k = *(const float4*)&g_bufK[d * DD + c];
    float4 q = *(const float4*)&g_bufQ[s * DD + c];
    float4 v = *(const float4*)&g_bufV[s * DD + c];
    float4 m;
    m.x = sigmoidf_fast(k.x + q.x) * v.x;
    m.y = sigmoidf_fast(k.y + q.y) * v.y;
    m.z = sigmoidf_fast(k.z + q.z) * v.z;
    m.w = sigmoidf_fast(k.w + q.w) * v.w;
    red_add_v4(&g_bufA[d * DD + c], m);
    if (count_deg && (gt & 7) == 0) atomicAdd(&g_deg[d], 1.0f);
}

// ---------------------------------------------------------------------------
// h = relu(agg + skip), float4
__global__ __launch_bounds__(256) void combine_relu_kernel(int NV)
{
    int t = blockIdx.x * blockDim.x + threadIdx.x;
    if (t >= NV) return;
    float4 a = ((const float4*)g_bufA)[t];
    float4 s = ((const float4*)g_bufS)[t];
    float4 r;
    r.x = fmaxf(a.x + s.x, 0.0f);
    r.y = fmaxf(a.y + s.y, 0.0f);
    r.z = fmaxf(a.z + s.z, 0.0f);
    r.w = fmaxf(a.w + s.w, 0.0f);
    ((float4*)g_bufH)[t] = r;
}

// ---------------------------------------------------------------------------
// FiLM node transform: transposed padded smem weights, LDS.128 reads
__global__ __launch_bounds__(256) void film_node_kernel(
    int N,
    const float* __restrict__ Wlin, const float* __restrict__ Wfilm,
    const float* __restrict__ bfilm,
    const float* __restrict__ Wls, const float* __restrict__ Wfs)
{
    __shared__ float sLin[DD * WSTRIDE];       // sLin[d*36 + j] = Wlin[j][d]
    __shared__ float sLs[DD * WSTRIDE];
    __shared__ float sFilm[2 * DD * WSTRIDE];  // sFilm[o*36 + j] = Wfilm[j][o]
    __shared__ float sFs[2 * DD * WSTRIDE];
    __shared__ float sbf[2 * DD];

    for (int idx = threadIdx.x; idx < DD * DD; idx += blockDim.x) {
        int j = idx >> 5, d = idx & 31;
        sLin[d * WSTRIDE + j] = Wlin[idx];
        sLs[d * WSTRIDE + j]  = Wls[idx];
    }
    for (int idx = threadIdx.x; idx < DD * 2 * DD; idx += blockDim.x) {
        int j = idx >> 6, o = idx & 63;
        sFilm[o * WSTRIDE + j] = Wfilm[idx];
        sFs[o * WSTRIDE + j]   = Wfs[idx];
    }
    if (threadIdx.x < 2 * DD) sbf[threadIdx.x] = bfilm[threadIdx.x];
    __syncthreads();

    int gt = blockIdx.x * blockDim.x + threadIdx.x;
    int i = gt >> 5;
    if (i >= N) return;
    int d = gt & 31;
    float h = g_bufH[i * DD + d];

    const float4* pLin = (const float4*)&sLin[d * WSTRIDE];
    const float4* pLs  = (const float4*)&sLs[d * WSTRIDE];
    const float4* pBe  = (const float4*)&sFilm[d * WSTRIDE];
    const float4* pGa  = (const float4*)&sFilm[(DD + d) * WSTRIDE];
    const float4* pBs  = (const float4*)&sFs[d * WSTRIDE];
    const float4* pGs  = (const float4*)&sFs[(DD + d) * WSTRIDE];

    float xl = 0.0f, be = sbf[d], ga = sbf[DD + d];
    float ls = 0.0f, bs = 0.0f, gs = 0.0f;
#pragma unroll
    for (int jb = 0; jb < 8; jb++) {
        float4 wl = pLin[jb], wls = pLs[jb];
        float4 wbe = pBe[jb], wga = pGa[jb];
        float4 wbs = pBs[jb], wgs = pGs[jb];
        float h0 = __shfl_sync(0xffffffffu, h, jb * 4 + 0);
        float h1 = __shfl_sync(0xffffffffu, h, jb * 4 + 1);
        float h2 = __shfl_sync(0xffffffffu, h, jb * 4 + 2);
        float h3 = __shfl_sync(0xffffffffu, h, jb * 4 + 3);
        xl = fmaf(h0, wl.x, xl);  xl = fmaf(h1, wl.y, xl);
        xl = fmaf(h2, wl.z, xl);  xl = fmaf(h3, wl.w, xl);
        be = fmaf(h0, wbe.x, be); be = fmaf(h1, wbe.y, be);
        be = fmaf(h2, wbe.z, be); be = fmaf(h3, wbe.w, be);
        ga = fmaf(h0, wga.x, ga); ga = fmaf(h1, wga.y, ga);
        ga = fmaf(h2, wga.z, ga); ga = fmaf(h3, wga.w, ga);
        ls = fmaf(h0, wls.x, ls); ls = fmaf(h1, wls.y, ls);
        ls = fmaf(h2, wls.z, ls); ls = fmaf(h3, wls.w, ls);
        bs = fmaf(h0, wbs.x, bs); bs = fmaf(h1, wbs.y, bs);
        bs = fmaf(h2, wbs.z, bs); bs = fmaf(h3, wbs.w, bs);
        gs = fmaf(h0, wgs.x, gs); gs = fmaf(h1, wgs.y, gs);
        gs = fmaf(h2, wgs.z, gs); gs = fmaf(h3, wgs.w, gs);
    }
    int t = i * DD + d;
    g_bufQ[t] = xl;
    g_bufK[t] = be;
    g_bufV[t] = ga;
    g_bufS[t] = fmaxf(fmaf(gs, ls, bs), 0.0f);
}

// ---------------------------------------------------------------------------
// FiLM edge pass, 8 lanes per edge
__global__ __launch_bounds__(256) void edge_film_kernel(
    const int* __restrict__ ei, int E)
{
    int gt = blockIdx.x * blockDim.x + threadIdx.x;
    int e = gt >> 3;
    if (e >= E) return;
    int c = (gt & 7) << 2;
    int s = __ldg(&ei[e]);
    int d = __ldg(&ei[E + e]);
    float4 ga = *(const float4*)&g_bufV[d * DD + c];
    float4 xl = *(const float4*)&g_bufQ[s * DD + c];
    float4 be = *(const float4*)&g_bufK[d * DD + c];
    float4 m;
    m.x = fmaxf(fmaf(ga.x, xl.x, be.x), 0.0f);
    m.y = fmaxf(fmaf(ga.y, xl.y, be.y), 0.0f);
    m.z = fmaxf(fmaf(ga.z, xl.z, be.z), 0.0f);
    m.w = fmaxf(fmaf(ga.w, xl.w, be.w), 0.0f);
    red_add_v4(&g_bufA[d * DD + c], m);
}

// ---------------------------------------------------------------------------
// FiLM combine + outer relu, float4: h = relu(skip + agg/max(deg,1))
__global__ __launch_bounds__(256) void film_combine_kernel(int NV)
{
    int t = blockIdx.x * blockDim.x + threadIdx.x;
    if (t >= NV) return;
    int i = t >> 3;   // 8 float4 per node
    float inv = __frcp_rn(fmaxf(g_deg[i], 1.0f));
    float4 a = ((const float4*)g_bufA)[t];
    float4 s = ((const float4*)g_bufS)[t];
    float4 r;
    r.x = fmaxf(fmaf(a.x, inv, s.x), 0.0f);
    r.y = fmaxf(fmaf(a.y, inv, s.y), 0.0f);
    r.z = fmaxf(fmaf(a.z, inv, s.z), 0.0f);
    r.w = fmaxf(fmaf(a.w, inv, s.w), 0.0f);
    ((float4*)g_bufH)[t] = r;
}

// ---------------------------------------------------------------------------
// Layer 3 node transform: 4 matrices, transposed padded smem
__global__ __launch_bounds__(256) void node3_kernel(
    int N,
    const float* __restrict__ Wk, const float* __restrict__ bk,
    const float* __restrict__ Wq, const float* __restrict__ bq,
    const float* __restrict__ Wv, const float* __restrict__ bv,
    const float* __restrict__ Ws, const float* __restrict__ b)
{
    __shared__ float sK[DD * WSTRIDE];
    __shared__ float sQ[DD * WSTRIDE];
    __shared__ float sV[DD * WSTRIDE];
    __shared__ float sS[DD * WSTRIDE];
    for (int idx = threadIdx.x; idx < DD * DD; idx += blockDim.x) {
        int j = idx >> 5, d = idx & 31;
        sK[d * WSTRIDE + j] = Wk[idx];
        sQ[d * WSTRIDE + j] = Wq[idx];
        sV[d * WSTRIDE + j] = Wv[idx];
        sS[d * WSTRIDE + j] = Ws[idx];
    }
    __syncthreads();

    int gt = blockIdx.x * blockDim.x + threadIdx.x;
    int i = gt >> 5;
    if (i >= N) return;
    int d = gt & 31;
    float h = g_bufH[i * DD + d];

    const float4* pK = (const float4*)&sK[d * WSTRIDE];
    const float4* pQ = (const float4*)&sQ[d * WSTRIDE];
    const float4* pV = (const float4*)&sV[d * WSTRIDE];
    const float4* pS = (const float4*)&sS[d * WSTRIDE];

    float k = __ldg(&bk[d]);
    float q = __ldg(&bq[d]);
    float v = __ldg(&bv[d]);
    float sk = __ldg(&b[d]);
#pragma unroll
    for (int jb = 0; jb < 8; jb++) {
        float4 wk = pK[jb], wq = pQ[jb], wv = pV[jb], ws = pS[jb];
        float h0 = __shfl_sync(0xffffffffu, h, jb * 4 + 0);
        float h1 = __shfl_sync(0xffffffffu, h, jb * 4 + 1);
        float h2 = __shfl_sync(0xffffffffu, h, jb * 4 + 2);
        float h3 = __shfl_sync(0xffffffffu, h, jb * 4 + 3);
        k  = fmaf(h0, wk.x, k);  k  = fmaf(h1, wk.y, k);
        k  = fmaf(h2, wk.z, k);  k  = fmaf(h3, wk.w, k);
        q  = fmaf(h0, wq.x, q);  q  = fmaf(h1, wq.y, q);
        q  = fmaf(h2, wq.z, q);  q  = fmaf(h3, wq.w, q);
        v  = fmaf(h0, wv.x, v);  v  = fmaf(h1, wv.y, v);
        v  = fmaf(h2, wv.z, v);  v  = fmaf(h3, wv.w, v);
        sk = fmaf(h0, ws.x, sk); sk = fmaf(h1, ws.y, sk);
        sk = fmaf(h2, ws.z, sk); sk = fmaf(h3, ws.w, sk);
    }
    int t = i * DD + d;
    g_bufK[t] = k;
    g_bufQ[t] = q;
    g_bufV[t] = v;
    g_bufS[t] = sk;
}

// ---------------------------------------------------------------------------
// Pool: h3 = agg + skip; gsum[batch[i]] += h3, 8 lanes per node
__global__ __launch_bounds__(256) void pool_kernel(
    const int* __restrict__ batch, int N)
{
    int gt = blockIdx.x * blockDim.x + threadIdx.x;
    int i = gt >> 3;
    if (i >= N) return;
    int c = (gt & 7) << 2;
    int t = i * DD + c;
    float4 a = *(const float4*)&g_bufA[t];
    float4 s = *(const float4*)&g_bufS[t];
    float4 r;
    r.x = a.x + s.x; r.y = a.y + s.y; r.z = a.z + s.z; r.w = a.w + s.w;
    int bgr = __ldg(&batch[i]);
    red_add_v4(&g_gsum[bgr * DD + c], r);
    if ((gt & 7) == 0) atomicAdd(&g_gcnt[bgr], 1.0f);
}

// ---------------------------------------------------------------------------
__global__ __launch_bounds__(128) void final_kernel(
    const float* __restrict__ linW, const float* __restrict__ linb,
    float* __restrict__ out, int G)
{
    __shared__ float sW[DD * CC];
    __shared__ float sb[CC];
    for (int j = threadIdx.x; j < DD * CC; j += blockDim.x) sW[j] = linW[j];
    if (threadIdx.x < CC) sb[threadIdx.x] = linb[threadIdx.x];
    __syncthreads();

    int g = blockIdx.x * blockDim.x + threadIdx.x;
    if (g >= G) return;
    float inv = __frcp_rn(fmaxf(g_gcnt[g], 1.0f));
    float acc[CC];
#pragma unroll
    for (int c = 0; c < CC; c++) acc[c] = sb[c];
#pragma unroll
    for (int j = 0; j < DD; j++) {
        float m = g_gsum[g * DD + j] * inv;
#pragma unroll
        for (int c = 0; c < CC; c++) acc[c] = fmaf(m, sW[j * CC + c], acc[c]);
    }
#pragma unroll
    for (int c = 0; c < CC; c++) out[g * CC + c] = acc[c];
}

// ---------------------------------------------------------------------------
static inline int nblk(long long threads, int tpb) {
    return (int)((threads + tpb - 1) / tpb);
}

extern "C" void kernel_launch(void* const* d_in, const int* in_sizes, int n_in,
                              void* d_out, int out_size)
{
    const float* x     = (const float*)d_in[0];
    const int*   ei    = (const int*)d_in[1];
    const int*   batch = (const int*)d_in[2];
    const float* c1_Wk = (const float*)d_in[4];
    const float* c1_bk = (const float*)d_in[5];
    const float* c1_Wq = (const float*)d_in[6];
    const float* c1_bq = (const float*)d_in[7];
    const float* c1_Wv = (const float*)d_in[8];
    const float* c1_bv = (const float*)d_in[9];
    const float* c1_Ws = (const float*)d_in[10];
    const float* c1_b  = (const float*)d_in[11];
    const float* c2_Wlin  = (const float*)d_in[12];
    const float* c2_Wfilm = (const float*)d_in[13];
    const float* c2_bfilm = (const float*)d_in[14];
    const float* c2_Wls   = (const float*)d_in[15];
    const float* c2_Wfs   = (const float*)d_in[16];
    const float* c3_Wk = (const float*)d_in[17];
    const float* c3_bk = (const float*)d_in[18];
    const float* c3_Wq = (const float*)d_in[19];
    const float* c3_bq = (const float*)d_in[20];
    const float* c3_Wv = (const float*)d_in[21];
    const float* c3_bv = (const float*)d_in[22];
    const float* c3_Ws = (const float*)d_in[23];
    const float* c3_b  = (const float*)d_in[24];
    const float* linW  = (const float*)d_in[25];
    const float* linb  = (const float*)d_in[26];
    float* out = (float*)d_out;

    int N = in_sizes[0];
    int E = in_sizes[1] / 2;
    int G = out_size / CC;

    void *pA, *pDeg, *pGs, *pGc;
    cudaGetSymbolAddress(&pA,   g_bufA);
    cudaGetSymbolAddress(&pDeg, g_deg);
    cudaGetSymbolAddress(&pGs,  g_gsum);
    cudaGetSymbolAddress(&pGc,  g_gcnt);

    const int TPB = 256;
    long long NT = (long long)N * DD;       // node-feature threads
    long long NV = NT / 4;                  // float4 threads
    long long E8 = (long long)E * 8;        // edge threads (8/edge)
    long long N8 = (long long)N * 8;

    // ---- Layer 1: ResGated(1 -> 32) ----
    node1_kernel<<<nblk(NT, TPB), TPB>>>(x, N, c1_Wk, c1_bk, c1_Wq, c1_bq,
                                         c1_Wv, c1_bv, c1_Ws, c1_b);
    cudaMemsetAsync(pA, 0, (size_t)NT * sizeof(float));
    cudaMemsetAsync(pDeg, 0, (size_t)N * sizeof(float));
    edge_resgated_kernel<<<nblk(E8, TPB), TPB>>>(ei, E, 1);
    combine_relu_kernel<<<nblk(NV, TPB), TPB>>>((int)NV);

    // ---- Layer 2: FiLM(32 -> 32) ----
    film_node_kernel<<<nblk(NT, TPB), TPB>>>(N, c2_Wlin, c2_Wfilm, c2_bfilm,
                                             c2_Wls, c2_Wfs);
    cudaMemsetAsync(pA, 0, (size_t)NT * sizeof(float));
    edge_film_kernel<<<nblk(E8, TPB), TPB>>>(ei, E);
    film_combine_kernel<<<nblk(NV, TPB), TPB>>>((int)NV);

    // ---- Layer 3: ResGated(32 -> 32), no final relu ----
    node3_kernel<<<nblk(NT, TPB), TPB>>>(N, c3_Wk, c3_bk, c3_Wq, c3_bq,
                                         c3_Wv, c3_bv, c3_Ws, c3_b);
    cudaMemsetAsync(pA, 0, (size_t)NT * sizeof(float));
    edge_resgated_kernel<<<nblk(E8, TPB), TPB>>>(ei, E, 0);

    // ---- Global mean pool + classifier ----
    cudaMemsetAsync(pGs, 0, (size_t)G * DD * sizeof(float));
    cudaMemsetAsync(pGc, 0, (size_t)G * sizeof(float));
    pool_kernel<<<nblk(N8, TPB), TPB>>>(batch, N);
    final_kernel<<<nblk(G, 128), 128>>>(linW, linb, out, G);
}

// round 7
// speedup vs baseline: 1.7441x; 1.0180x over previous
#include <cuda_runtime.h>
#include <math.h>

// Problem constants: N=100000, E=1600000, G=1024, D=32, C=10
#define DD 32
#define CC 10
#define MAX_N 100352
#define MAX_G 2048

// Scratch (alloc-free rule: __device__ globals)
__device__ float g_bufH[MAX_N * DD];   // film skip output
__device__ float g_bufK[MAX_N * DD];
__device__ float g_bufQ[MAX_N * DD];
__device__ float g_bufV[MAX_N * DD];
__device__ float g_bufS[MAX_N * DD];
__device__ float g_bufA[MAX_N * DD];
__device__ float g_deg[MAX_N];
__device__ float g_gsum[MAX_G * DD];
__device__ float g_gcnt[MAX_G];

typedef unsigned long long u64;

__device__ __forceinline__ u64 pack2(float lo, float hi) {
    u64 r;
    asm("mov.b64 %0, {%1, %2};" : "=l"(r) : "f"(lo), "f"(hi));
    return r;
}
__device__ __forceinline__ void unpack2(u64 v, float& lo, float& hi) {
    asm("mov.b64 {%0, %1}, %2;" : "=f"(lo), "=f"(hi) : "l"(v));
}
__device__ __forceinline__ u64 fma2(u64 a, u64 b, u64 c) {
    u64 d;
    asm("fma.rn.f32x2 %0, %1, %2, %3;" : "=l"(d) : "l"(a), "l"(b), "l"(c));
    return d;
}

__device__ __forceinline__ void red_add_v4(float* addr, float4 v) {
    asm volatile("red.global.add.v4.f32 [%0], {%1,%2,%3,%4};"
                 :: "l"(addr), "f"(v.x), "f"(v.y), "f"(v.z), "f"(v.w)
                 : "memory");
}

__device__ __forceinline__ float sigmoidf_fast(float x) {
    return __frcp_rn(1.0f + __expf(-x));
}

// ---------------------------------------------------------------------------
// Layer 1 node transform (F_IN = 1)
__global__ __launch_bounds__(256) void node1_kernel(
    const float* __restrict__ x, int N,
    const float* __restrict__ Wk, const float* __restrict__ bk,
    const float* __restrict__ Wq, const float* __restrict__ bq,
    const float* __restrict__ Wv, const float* __restrict__ bv,
    const float* __restrict__ Ws, const float* __restrict__ b)
{
    int t = blockIdx.x * blockDim.x + threadIdx.x;
    if (t >= N * DD) return;
    int i = t >> 5;
    int d = t & 31;
    float xv = __ldg(&x[i]);
    g_bufK[t] = fmaf(xv, __ldg(&Wk[d]), __ldg(&bk[d]));
    g_bufQ[t] = fmaf(xv, __ldg(&Wq[d]), __ldg(&bq[d]));
    g_bufV[t] = fmaf(xv, __ldg(&Wv[d]), __ldg(&bv[d]));
    g_bufS[t] = fmaf(xv, __ldg(&Ws[d]), __ldg(&b[d]));
}

// ---------------------------------------------------------------------------
// ResGated edge pass, 8 lanes per edge, float4 + vector red
__global__ __launch_bounds__(256) void edge_resgated_kernel(
    const int* __restrict__ ei, int E, int count_deg)
{
    int gt = blockIdx.x * blockDim.x + threadIdx.x;
    int e = gt >> 3;
    if (e >= E) return;
    int c = (gt & 7) << 2;
    int s = __ldg(&ei[e]);
    int d = __ldg(&ei[E + e]);
    float4 k = *(const float4*)&g_bufK[d * DD + c];
    float4 q = *(const float4*)&g_bufQ[s * DD + c];
    float4 v = *(const float4*)&g_bufV[s * DD + c];
    float4 m;
    m.x = sigmoidf_fast(k.x + q.x) * v.x;
    m.y = sigmoidf_fast(k.y + q.y) * v.y;
    m.z = sigmoidf_fast(k.z + q.z) * v.z;
    m.w = sigmoidf_fast(k.w + q.w) * v.w;
    red_add_v4(&g_bufA[d * DD + c], m);
    if (count_deg && (gt & 7) == 0) atomicAdd(&g_deg[d], 1.0f);
}

// ---------------------------------------------------------------------------
// FiLM node role A: computes xl = h@Wlin, beta/gamma = h@Wfilm + bfilm
// Input h = relu(bufA + bufS) (layer-1 combine fused here).
// Weights live in registers; warp grid-strides over nodes.
__global__ __launch_bounds__(256) void film_nodeA_kernel(
    int N, int nwarp,
    const float* __restrict__ Wlin, const float* __restrict__ Wfilm,
    const float* __restrict__ bfilm)
{
    int gt = blockIdx.x * blockDim.x + threadIdx.x;
    int w = gt >> 5;
    int d = gt & 31;

    u64 wp[DD];        // (Wlin[j][d], Wfilm_beta[j][d])
    float wg[DD];      // Wfilm_gamma[j][d]
#pragma unroll
    for (int j = 0; j < DD; j++) {
        wp[j] = pack2(__ldg(&Wlin[j * DD + d]), __ldg(&Wfilm[j * 2 * DD + d]));
        wg[j] = __ldg(&Wfilm[j * 2 * DD + DD + d]);
    }
    u64 bias2 = pack2(0.0f, __ldg(&bfilm[d]));
    float bga = __ldg(&bfilm[DD + d]);

    for (int i = w; i < N; i += nwarp) {
        int t = i * DD + d;
        float h = fmaxf(g_bufA[t] + g_bufS[t], 0.0f);
        u64 acc = bias2;
        float ga = bga;
#pragma unroll
        for (int j = 0; j < DD; j++) {
            float hj = __shfl_sync(0xffffffffu, h, j);
            u64 hh = pack2(hj, hj);
            acc = fma2(hh, wp[j], acc);
            ga = fmaf(hj, wg[j], ga);
        }
        float xl, be;
        unpack2(acc, xl, be);
        g_bufQ[t] = xl;
        g_bufK[t] = be;
        g_bufV[t] = ga;
    }
}

// ---------------------------------------------------------------------------
// FiLM node role B: skip = relu(gamma_s * (h@Wls) + beta_s), [b_s|g_s]=h@Wfs
// Input h = relu(bufA + bufS); output -> g_bufH
__global__ __launch_bounds__(256) void film_nodeB_kernel(
    int N, int nwarp,
    const float* __restrict__ Wls, const float* __restrict__ Wfs)
{
    int gt = blockIdx.x * blockDim.x + threadIdx.x;
    int w = gt >> 5;
    int d = gt & 31;

    u64 wp[DD];        // (Wls[j][d], Wfs_beta[j][d])
    float wg[DD];      // Wfs_gamma[j][d]
#pragma unroll
    for (int j = 0; j < DD; j++) {
        wp[j] = pack2(__ldg(&Wls[j * DD + d]), __ldg(&Wfs[j * 2 * DD + d]));
        wg[j] = __ldg(&Wfs[j * 2 * DD + DD + d]);
    }

    for (int i = w; i < N; i += nwarp) {
        int t = i * DD + d;
        float h = fmaxf(g_bufA[t] + g_bufS[t], 0.0f);
        u64 acc = 0;   // (0.0f, 0.0f)
        float gs = 0.0f;
#pragma unroll
        for (int j = 0; j < DD; j++) {
            float hj = __shfl_sync(0xffffffffu, h, j);
            u64 hh = pack2(hj, hj);
            acc = fma2(hh, wp[j], acc);
            gs = fmaf(hj, wg[j], gs);
        }
        float ls, bs;
        unpack2(acc, ls, bs);
        g_bufH[t] = fmaxf(fmaf(gs, ls, bs), 0.0f);
    }
}

// ---------------------------------------------------------------------------
// FiLM edge pass, 8 lanes per edge
__global__ __launch_bounds__(256) void edge_film_kernel(
    const int* __restrict__ ei, int E)
{
    int gt = blockIdx.x * blockDim.x + threadIdx.x;
    int e = gt >> 3;
    if (e >= E) return;
    int c = (gt & 7) << 2;
    int s = __ldg(&ei[e]);
    int d = __ldg(&ei[E + e]);
    float4 ga = *(const float4*)&g_bufV[d * DD + c];
    float4 xl = *(const float4*)&g_bufQ[s * DD + c];
    float4 be = *(const float4*)&g_bufK[d * DD + c];
    float4 m;
    m.x = fmaxf(fmaf(ga.x, xl.x, be.x), 0.0f);
    m.y = fmaxf(fmaf(ga.y, xl.y, be.y), 0.0f);
    m.z = fmaxf(fmaf(ga.z, xl.z, be.z), 0.0f);
    m.w = fmaxf(fmaf(ga.w, xl.w, be.w), 0.0f);
    red_add_v4(&g_bufA[d * DD + c], m);
}

// ---------------------------------------------------------------------------
// Layer-3 node roles: input h2 = relu(fma(agg, 1/max(deg,1), film_skip))
// (film combine fused). Two matrices per role, packed FMA2.
__global__ __launch_bounds__(256) void node3_role_kernel(
    int N, int nwarp,
    const float* __restrict__ W0, const float* __restrict__ b0,
    const float* __restrict__ W1, const float* __restrict__ b1,
    float* __restrict__ out0, float* __restrict__ out1)
{
    int gt = blockIdx.x * blockDim.x + threadIdx.x;
    int w = gt >> 5;
    int d = gt & 31;

    u64 wp[DD];
#pragma unroll
    for (int j = 0; j < DD; j++)
        wp[j] = pack2(__ldg(&W0[j * DD + d]), __ldg(&W1[j * DD + d]));
    u64 bias2 = pack2(__ldg(&b0[d]), __ldg(&b1[d]));

    for (int i = w; i < N; i += nwarp) {
        int t = i * DD + d;
        float inv = __frcp_rn(fmaxf(g_deg[i], 1.0f));
        float h = fmaxf(fmaf(g_bufA[t], inv, g_bufH[t]), 0.0f);
        u64 acc = bias2;
#pragma unroll
        for (int j = 0; j < DD; j++) {
            float hj = __shfl_sync(0xffffffffu, h, j);
            u64 hh = pack2(hj, hj);
            acc = fma2(hh, wp[j], acc);
        }
        float r0, r1;
        unpack2(acc, r0, r1);
        out0[t] = r0;
        out1[t] = r1;
    }
}

// ---------------------------------------------------------------------------
// Pool: h3 = agg + skip; gsum[batch[i]] += h3, 8 lanes per node
__global__ __launch_bounds__(256) void pool_kernel(
    const int* __restrict__ batch, int N)
{
    int gt = blockIdx.x * blockDim.x + threadIdx.x;
    int i = gt >> 3;
    if (i >= N) return;
    int c = (gt & 7) << 2;
    int t = i * DD + c;
    float4 a = *(const float4*)&g_bufA[t];
    float4 s = *(const float4*)&g_bufS[t];
    float4 r;
    r.x = a.x + s.x; r.y = a.y + s.y; r.z = a.z + s.z; r.w = a.w + s.w;
    int bgr = __ldg(&batch[i]);
    red_add_v4(&g_gsum[bgr * DD + c], r);
    if ((gt & 7) == 0) atomicAdd(&g_gcnt[bgr], 1.0f);
}

// ---------------------------------------------------------------------------
__global__ __launch_bounds__(128) void final_kernel(
    const float* __restrict__ linW, const float* __restrict__ linb,
    float* __restrict__ out, int G)
{
    __shared__ float sW[DD * CC];
    __shared__ float sb[CC];
    for (int j = threadIdx.x; j < DD * CC; j += blockDim.x) sW[j] = linW[j];
    if (threadIdx.x < CC) sb[threadIdx.x] = linb[threadIdx.x];
    __syncthreads();

    int g = blockIdx.x * blockDim.x + threadIdx.x;
    if (g >= G) return;
    float inv = __frcp_rn(fmaxf(g_gcnt[g], 1.0f));
    float acc[CC];
#pragma unroll
    for (int c = 0; c < CC; c++) acc[c] = sb[c];
#pragma unroll
    for (int j = 0; j < DD; j++) {
        float m = g_gsum[g * DD + j] * inv;
#pragma unroll
        for (int c = 0; c < CC; c++) acc[c] = fmaf(m, sW[j * CC + c], acc[c]);
    }
#pragma unroll
    for (int c = 0; c < CC; c++) out[g * CC + c] = acc[c];
}

// ---------------------------------------------------------------------------
static inline int nblk(long long threads, int tpb) {
    return (int)((threads + tpb - 1) / tpb);
}

extern "C" void kernel_launch(void* const* d_in, const int* in_sizes, int n_in,
                              void* d_out, int out_size)
{
    const float* x     = (const float*)d_in[0];
    const int*   ei    = (const int*)d_in[1];
    const int*   batch = (const int*)d_in[2];
    const float* c1_Wk = (const float*)d_in[4];
    const float* c1_bk = (const float*)d_in[5];
    const float* c1_Wq = (const float*)d_in[6];
    const float* c1_bq = (const float*)d_in[7];
    const float* c1_Wv = (const float*)d_in[8];
    const float* c1_bv = (const float*)d_in[9];
    const float* c1_Ws = (const float*)d_in[10];
    const float* c1_b  = (const float*)d_in[11];
    const float* c2_Wlin  = (const float*)d_in[12];
    const float* c2_Wfilm = (const float*)d_in[13];
    const float* c2_bfilm = (const float*)d_in[14];
    const float* c2_Wls   = (const float*)d_in[15];
    const float* c2_Wfs   = (const float*)d_in[16];
    const float* c3_Wk = (const float*)d_in[17];
    const float* c3_bk = (const float*)d_in[18];
    const float* c3_Wq = (const float*)d_in[19];
    const float* c3_bq = (const float*)d_in[20];
    const float* c3_Wv = (const float*)d_in[21];
    const float* c3_bv = (const float*)d_in[22];
    const float* c3_Ws = (const float*)d_in[23];
    const float* c3_b  = (const float*)d_in[24];
    const float* linW  = (const float*)d_in[25];
    const float* linb  = (const float*)d_in[26];
    float* out = (float*)d_out;

    int N = in_sizes[0];
    int E = in_sizes[1] / 2;
    int G = out_size / CC;

    void *pA, *pDeg, *pGs, *pGc;
    cudaGetSymbolAddress(&pA,   g_bufA);
    cudaGetSymbolAddress(&pDeg, g_deg);
    cudaGetSymbolAddress(&pGs,  g_gsum);
    cudaGetSymbolAddress(&pGc,  g_gcnt);

    const int TPB = 256;
    long long NT = (long long)N * DD;
    long long E8 = (long long)E * 8;
    long long N8 = (long long)N * 8;

    const int ROLE_BLOCKS = 384;               // grid-stride role kernels
    const int NWARP = ROLE_BLOCKS * (TPB / 32);

    // ---- Layer 1: ResGated(1 -> 32) ----
    node1_kernel<<<nblk(NT, TPB), TPB>>>(x, N, c1_Wk, c1_bk, c1_Wq, c1_bq,
                                         c1_Wv, c1_bv, c1_Ws, c1_b);
    cudaMemsetAsync(pA, 0, (size_t)NT * sizeof(float));
    cudaMemsetAsync(pDeg, 0, (size_t)N * sizeof(float));
    edge_resgated_kernel<<<nblk(E8, TPB), TPB>>>(ei, E, 1);

    // ---- Layer 2: FiLM(32 -> 32); layer-1 combine fused into roles ----
    film_nodeA_kernel<<<ROLE_BLOCKS, TPB>>>(N, NWARP, c2_Wlin, c2_Wfilm, c2_bfilm);
    film_nodeB_kernel<<<ROLE_BLOCKS, TPB>>>(N, NWARP, c2_Wls, c2_Wfs);
    cudaMemsetAsync(pA, 0, (size_t)NT * sizeof(float));
    edge_film_kernel<<<nblk(E8, TPB), TPB>>>(ei, E);

    // ---- Layer 3: ResGated(32 -> 32); film combine fused into roles ----
    void *pK, *pQ, *pV, *pS;
    cudaGetSymbolAddress(&pK, g_bufK);
    cudaGetSymbolAddress(&pQ, g_bufQ);
    cudaGetSymbolAddress(&pV, g_bufV);
    cudaGetSymbolAddress(&pS, g_bufS);
    node3_role_kernel<<<ROLE_BLOCKS, TPB>>>(N, NWARP, c3_Wk, c3_bk, c3_Wq, c3_bq,
                                            (float*)pK, (float*)pQ);
    node3_role_kernel<<<ROLE_BLOCKS, TPB>>>(N, NWARP, c3_Wv, c3_bv, c3_Ws, c3_b,
                                            (float*)pV, (float*)pS);
    cudaMemsetAsync(pA, 0, (size_t)NT * sizeof(float));
    edge_resgated_kernel<<<nblk(E8, TPB), TPB>>>(ei, E, 0);

    // ---- Global mean pool + classifier ----
    cudaMemsetAsync(pGs, 0, (size_t)G * DD * sizeof(float));
    cudaMemsetAsync(pGc, 0, (size_t)G * sizeof(float));
    pool_kernel<<<nblk(N8, TPB), TPB>>>(batch, N);
    final_kernel<<<nblk(G, 128), 128>>>(linW, linb, out, G);
}

// round 8
// speedup vs baseline: 2.1348x; 1.2241x over previous
#include <cuda_runtime.h>
#include <cuda_bf16.h>
#include <math.h>

// Problem constants: N=100000, E=1600000, G=1024, D=32, C=10
#define DD 32
#define CC 10
#define MAX_N 100352
#define MAX_G 2048

typedef unsigned long long u64;

// Scratch (alloc-free rule: __device__ globals)
// Edge-gathered operands in bf16 (halves gather traffic); accumulators fp32.
__device__ __align__(16) __nv_bfloat16 g_bK[MAX_N * DD];  // k / beta
__device__ __align__(16) __nv_bfloat16 g_bQ[MAX_N * DD];  // q / xl
__device__ __align__(16) __nv_bfloat16 g_bV[MAX_N * DD];  // v / gamma
__device__ float g_bufS[MAX_N * DD];   // skip path (fp32)
__device__ float g_bufH[MAX_N * DD];   // film skip output (fp32)
__device__ float g_bufA[MAX_N * DD];   // aggregation target (fp32)
__device__ float g_deg[MAX_N];
__device__ float g_gsum[MAX_G * DD];
__device__ float g_gcnt[MAX_G];

// ---------------------------------------------------------------------------
__device__ __forceinline__ u64 pack2(float lo, float hi) {
    u64 r;
    asm("mov.b64 %0, {%1, %2};" : "=l"(r) : "f"(lo), "f"(hi));
    return r;
}
__device__ __forceinline__ void unpack2(u64 v, float& lo, float& hi) {
    asm("mov.b64 {%0, %1}, %2;" : "=f"(lo), "=f"(hi) : "l"(v));
}
__device__ __forceinline__ u64 fma2(u64 a, u64 b, u64 c) {
    u64 d;
    asm("fma.rn.f32x2 %0, %1, %2, %3;" : "=l"(d) : "l"(a), "l"(b), "l"(c));
    return d;
}
__device__ __forceinline__ u64 add2(u64 a, u64 b) {
    u64 d;
    asm("add.rn.f32x2 %0, %1, %2;" : "=l"(d) : "l"(a), "l"(b));
    return d;
}
__device__ __forceinline__ void red_add_v4(float* addr, float4 v) {
    asm volatile("red.global.add.v4.f32 [%0], {%1,%2,%3,%4};"
                 :: "l"(addr), "f"(v.x), "f"(v.y), "f"(v.z), "f"(v.w)
                 : "memory");
}
__device__ __forceinline__ float sigmoidf_fast(float x) {
    return __frcp_rn(1.0f + __expf(-x));
}
// Load 4 consecutive bf16 (8B) and widen to float4.
__device__ __forceinline__ float4 ld_bf4(const __nv_bfloat16* base, int idx4) {
    uint2 r = __ldg(((const uint2*)base) + idx4);
    __nv_bfloat162 a = *reinterpret_cast<__nv_bfloat162*>(&r.x);
    __nv_bfloat162 b = *reinterpret_cast<__nv_bfloat162*>(&r.y);
    float2 fa = __bfloat1622float2(a);
    float2 fb = __bfloat1622float2(b);
    return make_float4(fa.x, fa.y, fb.x, fb.y);
}

union F4U2 { float4 f; u64 u[2]; };

// ---------------------------------------------------------------------------
// Layer 1 node transform (F_IN = 1): outputs bf16 k/q/v + fp32 skip
__global__ __launch_bounds__(256) void node1_kernel(
    const float* __restrict__ x, int N,
    const float* __restrict__ Wk, const float* __restrict__ bk,
    const float* __restrict__ Wq, const float* __restrict__ bq,
    const float* __restrict__ Wv, const float* __restrict__ bv,
    const float* __restrict__ Ws, const float* __restrict__ b)
{
    int t = blockIdx.x * blockDim.x + threadIdx.x;
    if (t >= N * DD) return;
    int i = t >> 5;
    int d = t & 31;
    float xv = __ldg(&x[i]);
    g_bK[t] = __float2bfloat16(fmaf(xv, __ldg(&Wk[d]), __ldg(&bk[d])));
    g_bQ[t] = __float2bfloat16(fmaf(xv, __ldg(&Wq[d]), __ldg(&bq[d])));
    g_bV[t] = __float2bfloat16(fmaf(xv, __ldg(&Wv[d]), __ldg(&bv[d])));
    g_bufS[t] = fmaf(xv, __ldg(&Ws[d]), __ldg(&b[d]));
}

// ---------------------------------------------------------------------------
// ResGated edge pass: 8 lanes/edge, bf16 gathers, fp32 vector reduction
__global__ __launch_bounds__(256) void edge_resgated_kernel(
    const int* __restrict__ ei, int E, int count_deg)
{
    int gt = blockIdx.x * blockDim.x + threadIdx.x;
    int e = gt >> 3;
    if (e >= E) return;
    int c = gt & 7;                 // feature quad 0..7
    int s = __ldg(&ei[e]);
    int d = __ldg(&ei[E + e]);
    float4 k = ld_bf4(g_bK, d * 8 + c);
    float4 q = ld_bf4(g_bQ, s * 8 + c);
    float4 v = ld_bf4(g_bV, s * 8 + c);
    float4 m;
    m.x = sigmoidf_fast(k.x + q.x) * v.x;
    m.y = sigmoidf_fast(k.y + q.y) * v.y;
    m.z = sigmoidf_fast(k.z + q.z) * v.z;
    m.w = sigmoidf_fast(k.w + q.w) * v.w;
    red_add_v4(&g_bufA[d * DD + (c << 2)], m);
    if (count_deg && c == 0) atomicAdd(&g_deg[d], 1.0f);
}

// ---------------------------------------------------------------------------
// FiLM edge pass: agg[dst] += relu(gamma[dst]*xl[src] + beta[dst])
__global__ __launch_bounds__(256) void edge_film_kernel(
    const int* __restrict__ ei, int E)
{
    int gt = blockIdx.x * blockDim.x + threadIdx.x;
    int e = gt >> 3;
    if (e >= E) return;
    int c = gt & 7;
    int s = __ldg(&ei[e]);
    int d = __ldg(&ei[E + e]);
    float4 ga = ld_bf4(g_bV, d * 8 + c);
    float4 xl = ld_bf4(g_bQ, s * 8 + c);
    float4 be = ld_bf4(g_bK, d * 8 + c);
    float4 m;
    m.x = fmaxf(fmaf(ga.x, xl.x, be.x), 0.0f);
    m.y = fmaxf(fmaf(ga.y, xl.y, be.y), 0.0f);
    m.z = fmaxf(fmaf(ga.z, xl.z, be.z), 0.0f);
    m.w = fmaxf(fmaf(ga.w, xl.w, be.w), 0.0f);
    red_add_v4(&g_bufA[d * DD + (c << 2)], m);
}

// ---------------------------------------------------------------------------
// FiLM node role A: xl = h@Wlin, beta/gamma = h@Wfilm + bfilm
// h = relu(bufA + bufS) (layer-1 combine fused).
// Weights in registers; h staged duplicated in smem; LDS.128 broadcast feeds
// fma2 directly; 4-way split accumulator chains.
__global__ __launch_bounds__(256) void film_nodeA_kernel(
    int N, int nwarp,
    const float* __restrict__ Wlin, const float* __restrict__ Wfilm,
    const float* __restrict__ bfilm)
{
    __shared__ float2 sh[8][2][DD];   // [warp][buf][j] = (h_j, h_j)
    int gt = blockIdx.x * blockDim.x + threadIdx.x;
    int w = gt >> 5;
    int d = gt & 31;
    int wl = threadIdx.x >> 5;

    u64 wp[DD];        // (Wlin[j][d], Wfilm_beta[j][d])
    float wg[DD];      // Wfilm_gamma[j][d]
#pragma unroll
    for (int j = 0; j < DD; j++) {
        wp[j] = pack2(__ldg(&Wlin[j * DD + d]), __ldg(&Wfilm[j * 2 * DD + d]));
        wg[j] = __ldg(&Wfilm[j * 2 * DD + DD + d]);
    }
    u64 bias2 = pack2(0.0f, __ldg(&bfilm[d]));
    float bga = __ldg(&bfilm[DD + d]);

    int buf = 0;
    for (int i = w; i < N; i += nwarp, buf ^= 1) {
        int t = i * DD + d;
        float h = fmaxf(g_bufA[t] + g_bufS[t], 0.0f);
        sh[wl][buf][d] = make_float2(h, h);
        __syncwarp();
        u64 a0 = bias2, a1 = 0, a2 = 0, a3 = 0;
        float g0 = bga, g1 = 0.0f, g2 = 0.0f, g3 = 0.0f;
#pragma unroll
        for (int jb = 0; jb < 8; jb++) {
            F4U2 h01, h23;
            h01.f = *(const float4*)&sh[wl][buf][jb * 4 + 0];
            h23.f = *(const float4*)&sh[wl][buf][jb * 4 + 2];
            int j = jb * 4;
            a0 = fma2(h01.u[0], wp[j + 0], a0);
            a1 = fma2(h01.u[1], wp[j + 1], a1);
            a2 = fma2(h23.u[0], wp[j + 2], a2);
            a3 = fma2(h23.u[1], wp[j + 3], a3);
            g0 = fmaf(h01.f.x, wg[j + 0], g0);
            g1 = fmaf(h01.f.z, wg[j + 1], g1);
            g2 = fmaf(h23.f.x, wg[j + 2], g2);
            g3 = fmaf(h23.f.z, wg[j + 3], g3);
        }
        u64 acc = add2(add2(a0, a1), add2(a2, a3));
        float xl, be;
        unpack2(acc, xl, be);
        float ga = (g0 + g1) + (g2 + g3);
        g_bQ[t] = __float2bfloat16(xl);
        g_bK[t] = __float2bfloat16(be);
        g_bV[t] = __float2bfloat16(ga);
    }
}

// ---------------------------------------------------------------------------
// FiLM node role B: skip = relu(gamma_s*(h@Wls) + beta_s), [b_s|g_s] = h@Wfs
// Output fp32 -> g_bufH
__global__ __launch_bounds__(256) void film_nodeB_kernel(
    int N, int nwarp,
    const float* __restrict__ Wls, const float* __restrict__ Wfs)
{
    __shared__ float2 sh[8][2][DD];
    int gt = blockIdx.x * blockDim.x + threadIdx.x;
    int w = gt >> 5;
    int d = gt & 31;
    int wl = threadIdx.x >> 5;

    u64 wp[DD];        // (Wls[j][d], Wfs_beta[j][d])
    float wg[DD];      // Wfs_gamma[j][d]
#pragma unroll
    for (int j = 0; j < DD; j++) {
        wp[j] = pack2(__ldg(&Wls[j * DD + d]), __ldg(&Wfs[j * 2 * DD + d]));
        wg[j] = __ldg(&Wfs[j * 2 * DD + DD + d]);
    }

    int buf = 0;
    for (int i = w; i < N; i += nwarp, buf ^= 1) {
        int t = i * DD + d;
        float h = fmaxf(g_bufA[t] + g_bufS[t], 0.0f);
        sh[wl][buf][d] = make_float2(h, h);
        __syncwarp();
        u64 a0 = 0, a1 = 0, a2 = 0, a3 = 0;
        float g0 = 0.0f, g1 = 0.0f, g2 = 0.0f, g3 = 0.0f;
#pragma unroll
        for (int jb = 0; jb < 8; jb++) {
            F4U2 h01, h23;
            h01.f = *(const float4*)&sh[wl][buf][jb * 4 + 0];
            h23.f = *(const float4*)&sh[wl][buf][jb * 4 + 2];
            int j = jb * 4;
            a0 = fma2(h01.u[0], wp[j + 0], a0);
            a1 = fma2(h01.u[1], wp[j + 1], a1);
            a2 = fma2(h23.u[0], wp[j + 2], a2);
            a3 = fma2(h23.u[1], wp[j + 3], a3);
            g0 = fmaf(h01.f.x, wg[j + 0], g0);
            g1 = fmaf(h01.f.z, wg[j + 1], g1);
            g2 = fmaf(h23.f.x, wg[j + 2], g2);
            g3 = fmaf(h23.f.z, wg[j + 3], g3);
        }
        u64 acc = add2(add2(a0, a1), add2(a2, a3));
        float ls, bs;
        unpack2(acc, ls, bs);
        float gs = (g0 + g1) + (g2 + g3);
        g_bufH[t] = fmaxf(fmaf(gs, ls, bs), 0.0f);
    }
}

// ---------------------------------------------------------------------------
// Layer-3 node role KQ: k,q = h2 @ {Wk,Wq} + {bk,bq}; outputs bf16.
// h2 = relu(fma(agg, 1/max(deg,1), film_skip)) (film combine fused).
__global__ __launch_bounds__(256) void node3_roleKQ_kernel(
    int N, int nwarp,
    const float* __restrict__ W0, const float* __restrict__ b0,
    const float* __restrict__ W1, const float* __restrict__ b1)
{
    __shared__ float2 sh[8][2][DD];
    int gt = blockIdx.x * blockDim.x + threadIdx.x;
    int w = gt >> 5;
    int d = gt & 31;
    int wl = threadIdx.x >> 5;

    u64 wp[DD];
#pragma unroll
    for (int j = 0; j < DD; j++)
        wp[j] = pack2(__ldg(&W0[j * DD + d]), __ldg(&W1[j * DD + d]));
    u64 bias2 = pack2(__ldg(&b0[d]), __ldg(&b1[d]));

    int buf = 0;
    for (int i = w; i < N; i += nwarp, buf ^= 1) {
        int t = i * DD + d;
        float inv = __frcp_rn(fmaxf(g_deg[i], 1.0f));
        float h = fmaxf(fmaf(g_bufA[t], inv, g_bufH[t]), 0.0f);
        sh[wl][buf][d] = make_float2(h, h);
        __syncwarp();
        u64 a0 = bias2, a1 = 0, a2 = 0, a3 = 0;
#pragma unroll
        for (int jb = 0; jb < 8; jb++) {
            F4U2 h01, h23;
            h01.f = *(const float4*)&sh[wl][buf][jb * 4 + 0];
            h23.f = *(const float4*)&sh[wl][buf][jb * 4 + 2];
            int j = jb * 4;
            a0 = fma2(h01.u[0], wp[j + 0], a0);
            a1 = fma2(h01.u[1], wp[j + 1], a1);
            a2 = fma2(h23.u[0], wp[j + 2], a2);
            a3 = fma2(h23.u[1], wp[j + 3], a3);
        }
        u64 acc = add2(add2(a0, a1), add2(a2, a3));
        float r0, r1;
        unpack2(acc, r0, r1);
        g_bK[t] = __float2bfloat16(r0);
        g_bQ[t] = __float2bfloat16(r1);
    }
}

// ---------------------------------------------------------------------------
// Layer-3 node role VS: v (bf16) and skip (fp32) = h2 @ {Wv,Ws} + {bv,b}
__global__ __launch_bounds__(256) void node3_roleVS_kernel(
    int N, int nwarp,
    const float* __restrict__ W0, const float* __restrict__ b0,
    const float* __restrict__ W1, const float* __restrict__ b1)
{
    __shared__ float2 sh[8][2][DD];
    int gt = blockIdx.x * blockDim.x + threadIdx.x;
    int w = gt >> 5;
    int d = gt & 31;
    int wl = threadIdx.x >> 5;

    u64 wp[DD];
#pragma unroll
    for (int j = 0; j < DD; j++)
        wp[j] = pack2(__ldg(&W0[j * DD + d]), __ldg(&W1[j * DD + d]));
    u64 bias2 = pack2(__ldg(&b0[d]), __ldg(&b1[d]));

    int buf = 0;
    for (int i = w; i < N; i += nwarp, buf ^= 1) {
        int t = i * DD + d;
        float inv = __frcp_rn(fmaxf(g_deg[i], 1.0f));
        float h = fmaxf(fmaf(g_bufA[t], inv, g_bufH[t]), 0.0f);
        sh[wl][buf][d] = make_float2(h, h);
        __syncwarp();
        u64 a0 = bias2, a1 = 0, a2 = 0, a3 = 0;
#pragma unroll
        for (int jb = 0; jb < 8; jb++) {
            F4U2 h01, h23;
            h01.f = *(const float4*)&sh[wl][buf][jb * 4 + 0];
            h23.f = *(const float4*)&sh[wl][buf][jb * 4 + 2];
            int j = jb * 4;
            a0 = fma2(h01.u[0], wp[j + 0], a0);
            a1 = fma2(h01.u[1], wp[j + 1], a1);
            a2 = fma2(h23.u[0], wp[j + 2], a2);
            a3 = fma2(h23.u[1], wp[j + 3], a3);
        }
        u64 acc = add2(add2(a0, a1), add2(a2, a3));
        float r0, r1;
        unpack2(acc, r0, r1);
        g_bV[t] = __float2bfloat16(r0);
        g_bufS[t] = r1;
    }
}

// ---------------------------------------------------------------------------
// Pool: h3 = agg + skip; gsum[batch[i]] += h3, 8 lanes per node
__global__ __launch_bounds__(256) void pool_kernel(
    const int* __restrict__ batch, int N)
{
    int gt = blockIdx.x * blockDim.x + threadIdx.x;
    int i = gt >> 3;
    if (i >= N) return;
    int c = (gt & 7) << 2;
    int t = i * DD + c;
    float4 a = *(const float4*)&g_bufA[t];
    float4 s = *(const float4*)&g_bufS[t];
    float4 r;
    r.x = a.x + s.x; r.y = a.y + s.y; r.z = a.z + s.z; r.w = a.w + s.w;
    int bgr = __ldg(&batch[i]);
    red_add_v4(&g_gsum[bgr * DD + c], r);
    if ((gt & 7) == 0) atomicAdd(&g_gcnt[bgr], 1.0f);
}

// ---------------------------------------------------------------------------
__global__ __launch_bounds__(128) void final_kernel(
    const float* __restrict__ linW, const float* __restrict__ linb,
    float* __restrict__ out, int G)
{
    __shared__ float sW[DD * CC];
    __shared__ float sb[CC];
    for (int j = threadIdx.x; j < DD * CC; j += blockDim.x) sW[j] = linW[j];
    if (threadIdx.x < CC) sb[threadIdx.x] = linb[threadIdx.x];
    __syncthreads();

    int g = blockIdx.x * blockDim.x + threadIdx.x;
    if (g >= G) return;
    float inv = __frcp_rn(fmaxf(g_gcnt[g], 1.0f));
    float acc[CC];
#pragma unroll
    for (int c = 0; c < CC; c++) acc[c] = sb[c];
#pragma unroll
    for (int j = 0; j < DD; j++) {
        float m = g_gsum[g * DD + j] * inv;
#pragma unroll
        for (int c = 0; c < CC; c++) acc[c] = fmaf(m, sW[j * CC + c], acc[c]);
    }
#pragma unroll
    for (int c = 0; c < CC; c++) out[g * CC + c] = acc[c];
}

// ---------------------------------------------------------------------------
static inline int nblk(long long threads, int tpb) {
    return (int)((threads + tpb - 1) / tpb);
}

extern "C" void kernel_launch(void* const* d_in, const int* in_sizes, int n_in,
                              void* d_out, int out_size)
{
    const float* x     = (const float*)d_in[0];
    const int*   ei    = (const int*)d_in[1];
    const int*   batch = (const int*)d_in[2];
    const float* c1_Wk = (const float*)d_in[4];
    const float* c1_bk = (const float*)d_in[5];
    const float* c1_Wq = (const float*)d_in[6];
    const float* c1_bq = (const float*)d_in[7];
    const float* c1_Wv = (const float*)d_in[8];
    const float* c1_bv = (const float*)d_in[9];
    const float* c1_Ws = (const float*)d_in[10];
    const float* c1_b  = (const float*)d_in[11];
    const float* c2_Wlin  = (const float*)d_in[12];
    const float* c2_Wfilm = (const float*)d_in[13];
    const float* c2_bfilm = (const float*)d_in[14];
    const float* c2_Wls   = (const float*)d_in[15];
    const float* c2_Wfs   = (const float*)d_in[16];
    const float* c3_Wk = (const float*)d_in[17];
    const float* c3_bk = (const float*)d_in[18];
    const float* c3_Wq = (const float*)d_in[19];
    const float* c3_bq = (const float*)d_in[20];
    const float* c3_Wv = (const float*)d_in[21];
    const float* c3_bv = (const float*)d_in[22];
    const float* c3_Ws = (const float*)d_in[23];
    const float* c3_b  = (const float*)d_in[24];
    const float* linW  = (const float*)d_in[25];
    const float* linb  = (const float*)d_in[26];
    float* out = (float*)d_out;

    int N = in_sizes[0];
    int E = in_sizes[1] / 2;
    int G = out_size / CC;

    void *pA, *pDeg, *pGs, *pGc;
    cudaGetSymbolAddress(&pA,   g_bufA);
    cudaGetSymbolAddress(&pDeg, g_deg);
    cudaGetSymbolAddress(&pGs,  g_gsum);
    cudaGetSymbolAddress(&pGc,  g_gcnt);

    const int TPB = 256;
    long long NT = (long long)N * DD;
    long long E8 = (long long)E * 8;
    long long N8 = (long long)N * 8;

    const int ROLE_BLOCKS = 296;                 // 2 blocks/SM on 148 SMs
    const int NWARP = ROLE_BLOCKS * (TPB / 32);

    // ---- Layer 1: ResGated(1 -> 32) ----
    node1_kernel<<<nblk(NT, TPB), TPB>>>(x, N, c1_Wk, c1_bk, c1_Wq, c1_bq,
                                         c1_Wv, c1_bv, c1_Ws, c1_b);
    cudaMemsetAsync(pA, 0, (size_t)NT * sizeof(float));
    cudaMemsetAsync(pDeg, 0, (size_t)N * sizeof(float));
    edge_resgated_kernel<<<nblk(E8, TPB), TPB>>>(ei, E, 1);

    // ---- Layer 2: FiLM(32 -> 32); layer-1 combine fused into roles ----
    film_nodeA_kernel<<<ROLE_BLOCKS, TPB>>>(N, NWARP, c2_Wlin, c2_Wfilm, c2_bfilm);
    film_nodeB_kernel<<<ROLE_BLOCKS, TPB>>>(N, NWARP, c2_Wls, c2_Wfs);
    cudaMemsetAsync(pA, 0, (size_t)NT * sizeof(float));
    edge_film_kernel<<<nblk(E8, TPB), TPB>>>(ei, E);

    // ---- Layer 3: ResGated(32 -> 32); film combine fused into roles ----
    node3_roleKQ_kernel<<<ROLE_BLOCKS, TPB>>>(N, NWARP, c3_Wk, c3_bk, c3_Wq, c3_bq);
    node3_roleVS_kernel<<<ROLE_BLOCKS, TPB>>>(N, NWARP, c3_Wv, c3_bv, c3_Ws, c3_b);
    cudaMemsetAsync(pA, 0, (size_t)NT * sizeof(float));
    edge_resgated_kernel<<<nblk(E8, TPB), TPB>>>(ei, E, 0);

    // ---- Global mean pool + classifier ----
    cudaMemsetAsync(pGs, 0, (size_t)G * DD * sizeof(float));
    cudaMemsetAsync(pGc, 0, (size_t)G * sizeof(float));
    pool_kernel<<<nblk(N8, TPB), TPB>>>(batch, N);
    final_kernel<<<nblk(G, 128), 128>>>(linW, linb, out, G);
}

// round 9
// speedup vs baseline: 2.3883x; 1.1187x over previous
#include <cuda_runtime.h>
#include <cuda_bf16.h>
#include <math.h>

// Problem constants: N=100000, E=1600000, G=1024, D=32, C=10
#define DD 32
#define CC 10
#define MAX_N 100352
#define MAX_G 2048

typedef unsigned long long u64;

// Scratch (alloc-free rule: __device__ globals)
__device__ __align__(16) __nv_bfloat16 g_bK[MAX_N * DD];  // k / beta
__device__ __align__(16) __nv_bfloat16 g_bQ[MAX_N * DD];  // q / xl
__device__ __align__(16) __nv_bfloat16 g_bV[MAX_N * DD];  // v / gamma
__device__ float g_bufS[MAX_N * DD];   // skip path (fp32)
__device__ float g_bufH[MAX_N * DD];   // film skip output (fp32)
__device__ float g_bufA[MAX_N * DD];   // aggregation target (fp32)
__device__ float g_deg[MAX_N];
__device__ float g_gsum[MAX_G * DD];
__device__ float g_gcnt[MAX_G];

// ---------------------------------------------------------------------------
__device__ __forceinline__ u64 pack2(float lo, float hi) {
    u64 r;
    asm("mov.b64 %0, {%1, %2};" : "=l"(r) : "f"(lo), "f"(hi));
    return r;
}
__device__ __forceinline__ void unpack2(u64 v, float& lo, float& hi) {
    asm("mov.b64 {%0, %1}, %2;" : "=f"(lo), "=f"(hi) : "l"(v));
}
__device__ __forceinline__ u64 fma2(u64 a, u64 b, u64 c) {
    u64 d;
    asm("fma.rn.f32x2 %0, %1, %2, %3;" : "=l"(d) : "l"(a), "l"(b), "l"(c));
    return d;
}
__device__ __forceinline__ u64 add2(u64 a, u64 b) {
    u64 d;
    asm("add.rn.f32x2 %0, %1, %2;" : "=l"(d) : "l"(a), "l"(b));
    return d;
}
__device__ __forceinline__ void red_add_v4(float* addr, float4 v) {
    asm volatile("red.global.add.v4.f32 [%0], {%1,%2,%3,%4};"
                 :: "l"(addr), "f"(v.x), "f"(v.y), "f"(v.z), "f"(v.w)
                 : "memory");
}
__device__ __forceinline__ float sigmoidf_fast(float x) {
    return __frcp_rn(1.0f + __expf(-x));
}
__device__ __forceinline__ float4 ld_bf4(const __nv_bfloat16* base, int idx4) {
    uint2 r = __ldg(((const uint2*)base) + idx4);
    __nv_bfloat162 a = *reinterpret_cast<__nv_bfloat162*>(&r.x);
    __nv_bfloat162 b = *reinterpret_cast<__nv_bfloat162*>(&r.y);
    float2 fa = __bfloat1622float2(a);
    float2 fb = __bfloat1622float2(b);
    return make_float4(fa.x, fa.y, fb.x, fb.y);
}

union F4U2 { float4 f; u64 u[2]; };

#define ROLE_TPB 128          // 4 warps/block; allows 3 blocks/SM at ~160 regs
#define ROLE_BLOCKS 444       // ~3 blocks/SM on 148 SMs

// ---------------------------------------------------------------------------
// Layer 1 node transform (F_IN = 1): outputs bf16 k/q/v + fp32 skip
__global__ __launch_bounds__(256) void node1_kernel(
    const float* __restrict__ x, int N,
    const float* __restrict__ Wk, const float* __restrict__ bk,
    const float* __restrict__ Wq, const float* __restrict__ bq,
    const float* __restrict__ Wv, const float* __restrict__ bv,
    const float* __restrict__ Ws, const float* __restrict__ b)
{
    int t = blockIdx.x * blockDim.x + threadIdx.x;
    if (t >= N * DD) return;
    int i = t >> 5;
    int d = t & 31;
    float xv = __ldg(&x[i]);
    g_bK[t] = __float2bfloat16(fmaf(xv, __ldg(&Wk[d]), __ldg(&bk[d])));
    g_bQ[t] = __float2bfloat16(fmaf(xv, __ldg(&Wq[d]), __ldg(&bq[d])));
    g_bV[t] = __float2bfloat16(fmaf(xv, __ldg(&Wv[d]), __ldg(&bv[d])));
    g_bufS[t] = fmaf(xv, __ldg(&Ws[d]), __ldg(&b[d]));
}

// ---------------------------------------------------------------------------
// ResGated edge pass: 8 lanes/edge, bf16 gathers, fp32 vector reduction
__global__ __launch_bounds__(256) void edge_resgated_kernel(
    const int* __restrict__ ei, int E, int count_deg)
{
    int gt = blockIdx.x * blockDim.x + threadIdx.x;
    int e = gt >> 3;
    if (e >= E) return;
    int c = gt & 7;
    int s = __ldg(&ei[e]);
    int d = __ldg(&ei[E + e]);
    float4 k = ld_bf4(g_bK, d * 8 + c);
    float4 q = ld_bf4(g_bQ, s * 8 + c);
    float4 v = ld_bf4(g_bV, s * 8 + c);
    float4 m;
    m.x = sigmoidf_fast(k.x + q.x) * v.x;
    m.y = sigmoidf_fast(k.y + q.y) * v.y;
    m.z = sigmoidf_fast(k.z + q.z) * v.z;
    m.w = sigmoidf_fast(k.w + q.w) * v.w;
    red_add_v4(&g_bufA[d * DD + (c << 2)], m);
    if (count_deg && c == 0) atomicAdd(&g_deg[d], 1.0f);
}

// ---------------------------------------------------------------------------
// FiLM edge pass: agg[dst] += relu(gamma[dst]*xl[src] + beta[dst])
__global__ __launch_bounds__(256) void edge_film_kernel(
    const int* __restrict__ ei, int E)
{
    int gt = blockIdx.x * blockDim.x + threadIdx.x;
    int e = gt >> 3;
    if (e >= E) return;
    int c = gt & 7;
    int s = __ldg(&ei[e]);
    int d = __ldg(&ei[E + e]);
    float4 ga = ld_bf4(g_bV, d * 8 + c);
    float4 xl = ld_bf4(g_bQ, s * 8 + c);
    float4 be = ld_bf4(g_bK, d * 8 + c);
    float4 m;
    m.x = fmaxf(fmaf(ga.x, xl.x, be.x), 0.0f);
    m.y = fmaxf(fmaf(ga.y, xl.y, be.y), 0.0f);
    m.z = fmaxf(fmaf(ga.z, xl.z, be.z), 0.0f);
    m.w = fmaxf(fmaf(ga.w, xl.w, be.w), 0.0f);
    red_add_v4(&g_bufA[d * DD + (c << 2)], m);
}

// ---------------------------------------------------------------------------
// Stage two nodes' h (duplicated) in smem; returns via shared array.
// sh layout: [warp][node(2)][DD] float2
// ---------------------------------------------------------------------------
// FiLM node role A: xl = h@Wlin, beta/gamma = h@Wfilm + bfilm
// 2 nodes per warp-iteration for ILP; h = relu(bufA + bufS) fused.
__global__ __launch_bounds__(ROLE_TPB) void film_nodeA_kernel(
    int N, int nwarp,
    const float* __restrict__ Wlin, const float* __restrict__ Wfilm,
    const float* __restrict__ bfilm)
{
    __shared__ float2 sh[ROLE_TPB / 32][2][DD];
    int gt = blockIdx.x * blockDim.x + threadIdx.x;
    int w = gt >> 5;
    int d = gt & 31;
    int wl = threadIdx.x >> 5;

    u64 wp[DD];        // (Wlin[j][d], Wfilm_beta[j][d])
    float wg[DD];      // Wfilm_gamma[j][d]
#pragma unroll
    for (int j = 0; j < DD; j++) {
        wp[j] = pack2(__ldg(&Wlin[j * DD + d]), __ldg(&Wfilm[j * 2 * DD + d]));
        wg[j] = __ldg(&Wfilm[j * 2 * DD + DD + d]);
    }
    u64 bias2 = pack2(0.0f, __ldg(&bfilm[d]));
    float bga = __ldg(&bfilm[DD + d]);

    for (int i0 = w * 2; i0 < N; i0 += nwarp * 2) {
        int i1 = i0 + 1;
        int t0 = i0 * DD + d;
        int t1 = i1 * DD + d;
        float hA0 = g_bufA[t0];
        float hS0 = g_bufS[t0];
        float hA1 = (i1 < N) ? g_bufA[t1] : 0.0f;
        float hS1 = (i1 < N) ? g_bufS[t1] : 0.0f;
        __syncwarp();
        sh[wl][0][d] = make_float2(fmaxf(hA0 + hS0, 0.0f), fmaxf(hA0 + hS0, 0.0f));
        float h1 = fmaxf(hA1 + hS1, 0.0f);
        sh[wl][1][d] = make_float2(h1, h1);
        __syncwarp();

        u64 a0 = bias2, a1 = 0, a2 = 0, a3 = 0;
        u64 b0 = bias2, b1 = 0, b2 = 0, b3 = 0;
        float ga0 = bga, ga1 = 0.0f, gb0 = bga, gb1 = 0.0f;
#pragma unroll
        for (int jb = 0; jb < 8; jb++) {
            F4U2 x01, x23, y01, y23;
            x01.f = *(const float4*)&sh[wl][0][jb * 4 + 0];
            x23.f = *(const float4*)&sh[wl][0][jb * 4 + 2];
            y01.f = *(const float4*)&sh[wl][1][jb * 4 + 0];
            y23.f = *(const float4*)&sh[wl][1][jb * 4 + 2];
            int j = jb * 4;
            a0 = fma2(x01.u[0], wp[j + 0], a0);
            b0 = fma2(y01.u[0], wp[j + 0], b0);
            a1 = fma2(x01.u[1], wp[j + 1], a1);
            b1 = fma2(y01.u[1], wp[j + 1], b1);
            a2 = fma2(x23.u[0], wp[j + 2], a2);
            b2 = fma2(y23.u[0], wp[j + 2], b2);
            a3 = fma2(x23.u[1], wp[j + 3], a3);
            b3 = fma2(y23.u[1], wp[j + 3], b3);
            ga0 = fmaf(x01.f.x, wg[j + 0], ga0); gb0 = fmaf(y01.f.x, wg[j + 0], gb0);
            ga1 = fmaf(x01.f.z, wg[j + 1], ga1); gb1 = fmaf(y01.f.z, wg[j + 1], gb1);
            ga0 = fmaf(x23.f.x, wg[j + 2], ga0); gb0 = fmaf(y23.f.x, wg[j + 2], gb0);
            ga1 = fmaf(x23.f.z, wg[j + 3], ga1); gb1 = fmaf(y23.f.z, wg[j + 3], gb1);
        }
        {
            u64 acc = add2(add2(a0, a1), add2(a2, a3));
            float xl, be; unpack2(acc, xl, be);
            g_bQ[t0] = __float2bfloat16(xl);
            g_bK[t0] = __float2bfloat16(be);
            g_bV[t0] = __float2bfloat16(ga0 + ga1);
        }
        if (i1 < N) {
            u64 acc = add2(add2(b0, b1), add2(b2, b3));
            float xl, be; unpack2(acc, xl, be);
            g_bQ[t1] = __float2bfloat16(xl);
            g_bK[t1] = __float2bfloat16(be);
            g_bV[t1] = __float2bfloat16(gb0 + gb1);
        }
    }
}

// ---------------------------------------------------------------------------
// FiLM node role B: skip = relu(gamma_s*(h@Wls) + beta_s), [b_s|g_s] = h@Wfs
__global__ __launch_bounds__(ROLE_TPB) void film_nodeB_kernel(
    int N, int nwarp,
    const float* __restrict__ Wls, const float* __restrict__ Wfs)
{
    __shared__ float2 sh[ROLE_TPB / 32][2][DD];
    int gt = blockIdx.x * blockDim.x + threadIdx.x;
    int w = gt >> 5;
    int d = gt & 31;
    int wl = threadIdx.x >> 5;

    u64 wp[DD];        // (Wls[j][d], Wfs_beta[j][d])
    float wg[DD];      // Wfs_gamma[j][d]
#pragma unroll
    for (int j = 0; j < DD; j++) {
        wp[j] = pack2(__ldg(&Wls[j * DD + d]), __ldg(&Wfs[j * 2 * DD + d]));
        wg[j] = __ldg(&Wfs[j * 2 * DD + DD + d]);
    }

    for (int i0 = w * 2; i0 < N; i0 += nwarp * 2) {
        int i1 = i0 + 1;
        int t0 = i0 * DD + d;
        int t1 = i1 * DD + d;
        float hA0 = g_bufA[t0];
        float hS0 = g_bufS[t0];
        float hA1 = (i1 < N) ? g_bufA[t1] : 0.0f;
        float hS1 = (i1 < N) ? g_bufS[t1] : 0.0f;
        __syncwarp();
        float h0 = fmaxf(hA0 + hS0, 0.0f);
        float h1 = fmaxf(hA1 + hS1, 0.0f);
        sh[wl][0][d] = make_float2(h0, h0);
        sh[wl][1][d] = make_float2(h1, h1);
        __syncwarp();

        u64 a0 = 0, a1 = 0, a2 = 0, a3 = 0;
        u64 b0 = 0, b1 = 0, b2 = 0, b3 = 0;
        float ga0 = 0.0f, ga1 = 0.0f, gb0 = 0.0f, gb1 = 0.0f;
#pragma unroll
        for (int jb = 0; jb < 8; jb++) {
            F4U2 x01, x23, y01, y23;
            x01.f = *(const float4*)&sh[wl][0][jb * 4 + 0];
            x23.f = *(const float4*)&sh[wl][0][jb * 4 + 2];
            y01.f = *(const float4*)&sh[wl][1][jb * 4 + 0];
            y23.f = *(const float4*)&sh[wl][1][jb * 4 + 2];
            int j = jb * 4;
            a0 = fma2(x01.u[0], wp[j + 0], a0);
            b0 = fma2(y01.u[0], wp[j + 0], b0);
            a1 = fma2(x01.u[1], wp[j + 1], a1);
            b1 = fma2(y01.u[1], wp[j + 1], b1);
            a2 = fma2(x23.u[0], wp[j + 2], a2);
            b2 = fma2(y23.u[0], wp[j + 2], b2);
            a3 = fma2(x23.u[1], wp[j + 3], a3);
            b3 = fma2(y23.u[1], wp[j + 3], b3);
            ga0 = fmaf(x01.f.x, wg[j + 0], ga0); gb0 = fmaf(y01.f.x, wg[j + 0], gb0);
            ga1 = fmaf(x01.f.z, wg[j + 1], ga1); gb1 = fmaf(y01.f.z, wg[j + 1], gb1);
            ga0 = fmaf(x23.f.x, wg[j + 2], ga0); gb0 = fmaf(y23.f.x, wg[j + 2], gb0);
            ga1 = fmaf(x23.f.z, wg[j + 3], ga1); gb1 = fmaf(y23.f.z, wg[j + 3], gb1);
        }
        {
            u64 acc = add2(add2(a0, a1), add2(a2, a3));
            float ls, bs; unpack2(acc, ls, bs);
            g_bufH[t0] = fmaxf(fmaf(ga0 + ga1, ls, bs), 0.0f);
        }
        if (i1 < N) {
            u64 acc = add2(add2(b0, b1), add2(b2, b3));
            float ls, bs; unpack2(acc, ls, bs);
            g_bufH[t1] = fmaxf(fmaf(gb0 + gb1, ls, bs), 0.0f);
        }
    }
}

// ---------------------------------------------------------------------------
// Layer-3 node role KQ: k,q (bf16) = h2 @ {Wk,Wq} + {bk,bq}
// h2 = relu(fma(agg, 1/max(deg,1), film_skip)) fused. 2 nodes per iteration.
__global__ __launch_bounds__(ROLE_TPB) void node3_roleKQ_kernel(
    int N, int nwarp,
    const float* __restrict__ W0, const float* __restrict__ b0,
    const float* __restrict__ W1, const float* __restrict__ b1)
{
    __shared__ float2 sh[ROLE_TPB / 32][2][DD];
    int gt = blockIdx.x * blockDim.x + threadIdx.x;
    int w = gt >> 5;
    int d = gt & 31;
    int wl = threadIdx.x >> 5;

    u64 wp[DD];
#pragma unroll
    for (int j = 0; j < DD; j++)
        wp[j] = pack2(__ldg(&W0[j * DD + d]), __ldg(&W1[j * DD + d]));
    u64 bias2 = pack2(__ldg(&b0[d]), __ldg(&b1[d]));

    for (int i0 = w * 2; i0 < N; i0 += nwarp * 2) {
        int i1 = i0 + 1;
        int t0 = i0 * DD + d;
        int t1 = i1 * DD + d;
        float inv0 = __frcp_rn(fmaxf(g_deg[i0], 1.0f));
        float hA0 = g_bufA[t0];
        float hH0 = g_bufH[t0];
        float inv1 = (i1 < N) ? __frcp_rn(fmaxf(g_deg[i1], 1.0f)) : 1.0f;
        float hA1 = (i1 < N) ? g_bufA[t1] : 0.0f;
        float hH1 = (i1 < N) ? g_bufH[t1] : 0.0f;
        __syncwarp();
        float h0 = fmaxf(fmaf(hA0, inv0, hH0), 0.0f);
        float h1 = fmaxf(fmaf(hA1, inv1, hH1), 0.0f);
        sh[wl][0][d] = make_float2(h0, h0);
        sh[wl][1][d] = make_float2(h1, h1);
        __syncwarp();

        u64 a0 = bias2, a1 = 0, a2 = 0, a3 = 0;
        u64 b0v = bias2, b1v = 0, b2v = 0, b3v = 0;
#pragma unroll
        for (int jb = 0; jb < 8; jb++) {
            F4U2 x01, x23, y01, y23;
            x01.f = *(const float4*)&sh[wl][0][jb * 4 + 0];
            x23.f = *(const float4*)&sh[wl][0][jb * 4 + 2];
            y01.f = *(const float4*)&sh[wl][1][jb * 4 + 0];
            y23.f = *(const float4*)&sh[wl][1][jb * 4 + 2];
            int j = jb * 4;
            a0  = fma2(x01.u[0], wp[j + 0], a0);
            b0v = fma2(y01.u[0], wp[j + 0], b0v);
            a1  = fma2(x01.u[1], wp[j + 1], a1);
            b1v = fma2(y01.u[1], wp[j + 1], b1v);
            a2  = fma2(x23.u[0], wp[j + 2], a2);
            b2v = fma2(y23.u[0], wp[j + 2], b2v);
            a3  = fma2(x23.u[1], wp[j + 3], a3);
            b3v = fma2(y23.u[1], wp[j + 3], b3v);
        }
        {
            u64 acc = add2(add2(a0, a1), add2(a2, a3));
            float r0, r1; unpack2(acc, r0, r1);
            g_bK[t0] = __float2bfloat16(r0);
            g_bQ[t0] = __float2bfloat16(r1);
        }
        if (i1 < N) {
            u64 acc = add2(add2(b0v, b1v), add2(b2v, b3v));
            float r0, r1; unpack2(acc, r0, r1);
            g_bK[t1] = __float2bfloat16(r0);
            g_bQ[t1] = __float2bfloat16(r1);
        }
    }
}

// ---------------------------------------------------------------------------
// Layer-3 node role VS: v (bf16) and skip (fp32) = h2 @ {Wv,Ws} + {bv,b}
__global__ __launch_bounds__(ROLE_TPB) void node3_roleVS_kernel(
    int N, int nwarp,
    const float* __restrict__ W0, const float* __restrict__ b0,
    const float* __restrict__ W1, const float* __restrict__ b1)
{
    __shared__ float2 sh[ROLE_TPB / 32][2][DD];
    int gt = blockIdx.x * blockDim.x + threadIdx.x;
    int w = gt >> 5;
    int d = gt & 31;
    int wl = threadIdx.x >> 5;

    u64 wp[DD];
#pragma unroll
    for (int j = 0; j < DD; j++)
        wp[j] = pack2(__ldg(&W0[j * DD + d]), __ldg(&W1[j * DD + d]));
    u64 bias2 = pack2(__ldg(&b0[d]), __ldg(&b1[d]));

    for (int i0 = w * 2; i0 < N; i0 += nwarp * 2) {
        int i1 = i0 + 1;
        int t0 = i0 * DD + d;
        int t1 = i1 * DD + d;
        float inv0 = __frcp_rn(fmaxf(g_deg[i0], 1.0f));
        float hA0 = g_bufA[t0];
        float hH0 = g_bufH[t0];
        float inv1 = (i1 < N) ? __frcp_rn(fmaxf(g_deg[i1], 1.0f)) : 1.0f;
        float hA1 = (i1 < N) ? g_bufA[t1] : 0.0f;
        float hH1 = (i1 < N) ? g_bufH[t1] : 0.0f;
        __syncwarp();
        float h0 = fmaxf(fmaf(hA0, inv0, hH0), 0.0f);
        float h1 = fmaxf(fmaf(hA1, inv1, hH1), 0.0f);
        sh[wl][0][d] = make_float2(h0, h0);
        sh[wl][1][d] = make_float2(h1, h1);
        __syncwarp();

        u64 a0 = bias2, a1 = 0, a2 = 0, a3 = 0;
        u64 b0v = bias2, b1v = 0, b2v = 0, b3v = 0;
#pragma unroll
        for (int jb = 0; jb < 8; jb++) {
            F4U2 x01, x23, y01, y23;
            x01.f = *(const float4*)&sh[wl][0][jb * 4 + 0];
            x23.f = *(const float4*)&sh[wl][0][jb * 4 + 2];
            y01.f = *(const float4*)&sh[wl][1][jb * 4 + 0];
            y23.f = *(const float4*)&sh[wl][1][jb * 4 + 2];
            int j = jb * 4;
            a0  = fma2(x01.u[0], wp[j + 0], a0);
            b0v = fma2(y01.u[0], wp[j + 0], b0v);
            a1  = fma2(x01.u[1], wp[j + 1], a1);
            b1v = fma2(y01.u[1], wp[j + 1], b1v);
            a2  = fma2(x23.u[0], wp[j + 2], a2);
            b2v = fma2(y23.u[0], wp[j + 2], b2v);
            a3  = fma2(x23.u[1], wp[j + 3], a3);
            b3v = fma2(y23.u[1], wp[j + 3], b3v);
        }
        {
            u64 acc = add2(add2(a0, a1), add2(a2, a3));
            float r0, r1; unpack2(acc, r0, r1);
            g_bV[t0] = __float2bfloat16(r0);
            g_bufS[t0] = r1;
        }
        if (i1 < N) {
            u64 acc = add2(add2(b0v, b1v), add2(b2v, b3v));
            float r0, r1; unpack2(acc, r0, r1);
            g_bV[t1] = __float2bfloat16(r0);
            g_bufS[t1] = r1;
        }
    }
}

// ---------------------------------------------------------------------------
// Pool: h3 = agg + skip; gsum[batch[i]] += h3, 8 lanes per node
__global__ __launch_bounds__(256) void pool_kernel(
    const int* __restrict__ batch, int N)
{
    int gt = blockIdx.x * blockDim.x + threadIdx.x;
    int i = gt >> 3;
    if (i >= N) return;
    int c = (gt & 7) << 2;
    int t = i * DD + c;
    float4 a = *(const float4*)&g_bufA[t];
    float4 s = *(const float4*)&g_bufS[t];
    float4 r;
    r.x = a.x + s.x; r.y = a.y + s.y; r.z = a.z + s.z; r.w = a.w + s.w;
    int bgr = __ldg(&batch[i]);
    red_add_v4(&g_gsum[bgr * DD + c], r);
    if ((gt & 7) == 0) atomicAdd(&g_gcnt[bgr], 1.0f);
}

// ---------------------------------------------------------------------------
__global__ __launch_bounds__(128) void final_kernel(
    const float* __restrict__ linW, const float* __restrict__ linb,
    float* __restrict__ out, int G)
{
    __shared__ float sW[DD * CC];
    __shared__ float sb[CC];
    for (int j = threadIdx.x; j < DD * CC; j += blockDim.x) sW[j] = linW[j];
    if (threadIdx.x < CC) sb[threadIdx.x] = linb[threadIdx.x];
    __syncthreads();

    int g = blockIdx.x * blockDim.x + threadIdx.x;
    if (g >= G) return;
    float inv = __frcp_rn(fmaxf(g_gcnt[g], 1.0f));
    float acc[CC];
#pragma unroll
    for (int c = 0; c < CC; c++) acc[c] = sb[c];
#pragma unroll
    for (int j = 0; j < DD; j++) {
        float m = g_gsum[g * DD + j] * inv;
#pragma unroll
        for (int c = 0; c < CC; c++) acc[c] = fmaf(m, sW[j * CC + c], acc[c]);
    }
#pragma unroll
    for (int c = 0; c < CC; c++) out[g * CC + c] = acc[c];
}

// ---------------------------------------------------------------------------
static inline int nblk(long long threads, int tpb) {
    return (int)((threads + tpb - 1) / tpb);
}

extern "C" void kernel_launch(void* const* d_in, const int* in_sizes, int n_in,
                              void* d_out, int out_size)
{
    const float* x     = (const float*)d_in[0];
    const int*   ei    = (const int*)d_in[1];
    const int*   batch = (const int*)d_in[2];
    const float* c1_Wk = (const float*)d_in[4];
    const float* c1_bk = (const float*)d_in[5];
    const float* c1_Wq = (const float*)d_in[6];
    const float* c1_bq = (const float*)d_in[7];
    const float* c1_Wv = (const float*)d_in[8];
    const float* c1_bv = (const float*)d_in[9];
    const float* c1_Ws = (const float*)d_in[10];
    const float* c1_b  = (const float*)d_in[11];
    const float* c2_Wlin  = (const float*)d_in[12];
    const float* c2_Wfilm = (const float*)d_in[13];
    const float* c2_bfilm = (const float*)d_in[14];
    const float* c2_Wls   = (const float*)d_in[15];
    const float* c2_Wfs   = (const float*)d_in[16];
    const float* c3_Wk = (const float*)d_in[17];
    const float* c3_bk = (const float*)d_in[18];
    const float* c3_Wq = (const float*)d_in[19];
    const float* c3_bq = (const float*)d_in[20];
    const float* c3_Wv = (const float*)d_in[21];
    const float* c3_bv = (const float*)d_in[22];
    const float* c3_Ws = (const float*)d_in[23];
    const float* c3_b  = (const float*)d_in[24];
    const float* linW  = (const float*)d_in[25];
    const float* linb  = (const float*)d_in[26];
    float* out = (float*)d_out;

    int N = in_sizes[0];
    int E = in_sizes[1] / 2;
    int G = out_size / CC;

    void *pA, *pDeg, *pGs, *pGc;
    cudaGetSymbolAddress(&pA,   g_bufA);
    cudaGetSymbolAddress(&pDeg, g_deg);
    cudaGetSymbolAddress(&pGs,  g_gsum);
    cudaGetSymbolAddress(&pGc,  g_gcnt);

    const int TPB = 256;
    long long NT = (long long)N * DD;
    long long E8 = (long long)E * 8;
    long long N8 = (long long)N * 8;

    const int NWARP = ROLE_BLOCKS * (ROLE_TPB / 32);

    // ---- Layer 1: ResGated(1 -> 32) ----
    node1_kernel<<<nblk(NT, TPB), TPB>>>(x, N, c1_Wk, c1_bk, c1_Wq, c1_bq,
                                         c1_Wv, c1_bv, c1_Ws, c1_b);
    cudaMemsetAsync(pA, 0, (size_t)NT * sizeof(float));
    cudaMemsetAsync(pDeg, 0, (size_t)N * sizeof(float));
    edge_resgated_kernel<<<nblk(E8, TPB), TPB>>>(ei, E, 1);

    // ---- Layer 2: FiLM(32 -> 32); layer-1 combine fused into roles ----
    film_nodeA_kernel<<<ROLE_BLOCKS, ROLE_TPB>>>(N, NWARP, c2_Wlin, c2_Wfilm, c2_bfilm);
    film_nodeB_kernel<<<ROLE_BLOCKS, ROLE_TPB>>>(N, NWARP, c2_Wls, c2_Wfs);
    cudaMemsetAsync(pA, 0, (size_t)NT * sizeof(float));
    edge_film_kernel<<<nblk(E8, TPB), TPB>>>(ei, E);

    // ---- Layer 3: ResGated(32 -> 32); film combine fused into roles ----
    node3_roleKQ_kernel<<<ROLE_BLOCKS, ROLE_TPB>>>(N, NWARP, c3_Wk, c3_bk, c3_Wq, c3_bq);
    node3_roleVS_kernel<<<ROLE_BLOCKS, ROLE_TPB>>>(N, NWARP, c3_Wv, c3_bv, c3_Ws, c3_b);
    cudaMemsetAsync(pA, 0, (size_t)NT * sizeof(float));
    edge_resgated_kernel<<<nblk(E8, TPB), TPB>>>(ei, E, 0);

    // ---- Global mean pool + classifier ----
    cudaMemsetAsync(pGs, 0, (size_t)G * DD * sizeof(float));
    cudaMemsetAsync(pGc, 0, (size_t)G * sizeof(float));
    pool_kernel<<<nblk(N8, TPB), TPB>>>(batch, N);
    final_kernel<<<nblk(G, 128), 128>>>(linW, linb, out, G);
}

// round 11
// speedup vs baseline: 2.5196x; 1.0550x over previous
#include <cuda_runtime.h>
#include <cuda_bf16.h>
#include <math.h>

// Problem constants: N=100000, E=1600000, G=1024, D=32, C=10
#define DD 32
#define CC 10
#define MAX_N 100352
#define MAX_G 2048

typedef unsigned long long u64;
typedef unsigned int u32;

// Scratch (alloc-free rule: __device__ globals)
__device__ __align__(16) __nv_bfloat16 g_bK[MAX_N * DD];  // k / beta
__device__ __align__(16) __nv_bfloat16 g_bQ[MAX_N * DD];  // q / xl
__device__ __align__(16) __nv_bfloat16 g_bV[MAX_N * DD];  // v / gamma
__device__ float g_bufS[MAX_N * DD];   // skip path (fp32)
__device__ float g_bufH[MAX_N * DD];   // film skip output (fp32)
__device__ float g_bufA[MAX_N * DD];   // aggregation target (fp32)
__device__ float g_deg[MAX_N];
__device__ float g_gsum[MAX_G * DD];
__device__ float g_gcnt[MAX_G];

// ---------------------------------------------------------------------------
__device__ __forceinline__ void red_add_v4(float* addr, float4 v) {
    asm volatile("red.global.add.v4.f32 [%0], {%1,%2,%3,%4};"
                 :: "l"(addr), "f"(v.x), "f"(v.y), "f"(v.z), "f"(v.w)
                 : "memory");
}
__device__ __forceinline__ float sigmoidf_fast(float x) {
    return __frcp_rn(1.0f + __expf(-x));
}
__device__ __forceinline__ float4 ld_bf4(const __nv_bfloat16* base, int idx4) {
    uint2 r = __ldg(((const uint2*)base) + idx4);
    __nv_bfloat162 a = *reinterpret_cast<__nv_bfloat162*>(&r.x);
    __nv_bfloat162 b = *reinterpret_cast<__nv_bfloat162*>(&r.y);
    float2 fa = __bfloat1622float2(a);
    float2 fb = __bfloat1622float2(b);
    return make_float4(fa.x, fa.y, fb.x, fb.y);
}
__device__ __forceinline__ u32 pack_bf2(float lo, float hi) {
    __nv_bfloat162 h = __floats2bfloat162_rn(lo, hi);
    return *reinterpret_cast<u32*>(&h);
}
__device__ __forceinline__ u32 f2tf32(float f) {
    u32 r;
    asm("cvt.rna.tf32.f32 %0, %1;" : "=r"(r) : "f"(f));
    return r;
}
// mma.sync m16n8k8 row.col f32.tf32.tf32.f32
__device__ __forceinline__ void mma_tf32(
    float& d0, float& d1, float& d2, float& d3,
    u32 a0, u32 a1, u32 a2, u32 a3, u32 b0, u32 b1,
    float c0, float c1, float c2, float c3)
{
    asm volatile(
        "mma.sync.aligned.m16n8k8.row.col.f32.tf32.tf32.f32 "
        "{%0,%1,%2,%3}, {%4,%5,%6,%7}, {%8,%9}, {%10,%11,%12,%13};"
        : "=f"(d0), "=f"(d1), "=f"(d2), "=f"(d3)
        : "r"(a0), "r"(a1), "r"(a2), "r"(a3), "r"(b0), "r"(b1),
          "f"(c0), "f"(c1), "f"(c2), "f"(c3));
}

// ---------------------------------------------------------------------------
// Layer 1 node transform (F_IN = 1): outputs bf16 k/q/v + fp32 skip
__global__ __launch_bounds__(256) void node1_kernel(
    const float* __restrict__ x, int N,
    const float* __restrict__ Wk, const float* __restrict__ bk,
    const float* __restrict__ Wq, const float* __restrict__ bq,
    const float* __restrict__ Wv, const float* __restrict__ bv,
    const float* __restrict__ Ws, const float* __restrict__ b)
{
    int t = blockIdx.x * blockDim.x + threadIdx.x;
    if (t >= N * DD) return;
    int i = t >> 5;
    int d = t & 31;
    float xv = __ldg(&x[i]);
    g_bK[t] = __float2bfloat16(fmaf(xv, __ldg(&Wk[d]), __ldg(&bk[d])));
    g_bQ[t] = __float2bfloat16(fmaf(xv, __ldg(&Wq[d]), __ldg(&bq[d])));
    g_bV[t] = __float2bfloat16(fmaf(xv, __ldg(&Wv[d]), __ldg(&bv[d])));
    g_bufS[t] = fmaf(xv, __ldg(&Ws[d]), __ldg(&b[d]));
}

// ---------------------------------------------------------------------------
// ResGated edge pass: 8 lanes/edge, bf16 gathers, fp32 vector reduction
__global__ __launch_bounds__(256) void edge_resgated_kernel(
    const int* __restrict__ ei, int E, int count_deg)
{
    int gt = blockIdx.x * blockDim.x + threadIdx.x;
    int e = gt >> 3;
    if (e >= E) return;
    int c = gt & 7;
    int s = __ldg(&ei[e]);
    int d = __ldg(&ei[E + e]);
    float4 k = ld_bf4(g_bK, d * 8 + c);
    float4 q = ld_bf4(g_bQ, s * 8 + c);
    float4 v = ld_bf4(g_bV, s * 8 + c);
    float4 m;
    m.x = sigmoidf_fast(k.x + q.x) * v.x;
    m.y = sigmoidf_fast(k.y + q.y) * v.y;
    m.z = sigmoidf_fast(k.z + q.z) * v.z;
    m.w = sigmoidf_fast(k.w + q.w) * v.w;
    red_add_v4(&g_bufA[d * DD + (c << 2)], m);
    if (count_deg && c == 0) atomicAdd(&g_deg[d], 1.0f);
}

// ---------------------------------------------------------------------------
// FiLM edge pass: agg[dst] += relu(gamma[dst]*xl[src] + beta[dst])
__global__ __launch_bounds__(256) void edge_film_kernel(
    const int* __restrict__ ei, int E)
{
    int gt = blockIdx.x * blockDim.x + threadIdx.x;
    int e = gt >> 3;
    if (e >= E) return;
    int c = gt & 7;
    int s = __ldg(&ei[e]);
    int d = __ldg(&ei[E + e]);
    float4 ga = ld_bf4(g_bV, d * 8 + c);
    float4 xl = ld_bf4(g_bQ, s * 8 + c);
    float4 be = ld_bf4(g_bK, d * 8 + c);
    float4 m;
    m.x = fmaxf(fmaf(ga.x, xl.x, be.x), 0.0f);
    m.y = fmaxf(fmaf(ga.y, xl.y, be.y), 0.0f);
    m.z = fmaxf(fmaf(ga.z, xl.z, be.z), 0.0f);
    m.w = fmaxf(fmaf(ga.w, xl.w, be.w), 0.0f);
    red_add_v4(&g_bufA[d * DD + (c << 2)], m);
}

// ---------------------------------------------------------------------------
// FiLM node transform via tensor cores (tf32, m16n8k8, 4 k-steps).
// Fused output matrix W_all [32 x 192]:
//   cols 0-31: Wlin | 32-63: film beta(+b) | 64-95: film gamma(+b)
//   96-127: Wls | 128-159: fs beta | 160-191: fs gamma
// Block = 128 threads, one 16-node tile per block; warp w covers cols
// [48w, 48w+48) as 6 n-tiles.
__global__ __launch_bounds__(128) void film_mma_kernel(
    int N,
    const float* __restrict__ Wlin, const float* __restrict__ Wfilm,
    const float* __restrict__ bfilm,
    const float* __restrict__ Wls, const float* __restrict__ Wfs)
{
    __shared__ u32 sh_h[16][33];              // h tile as tf32 words, padded
    __shared__ float sout[16][200];           // 192 cols + pad

    int tid = threadIdx.x;
    int lane = tid & 31;
    int warp = tid >> 5;
    int g = lane >> 2;      // 0..7
    int tq = lane & 3;      // 0..3
    int i0 = blockIdx.x * 16;

    auto getW = [&](int k, int c) -> float {
        if (c < 32)       return __ldg(&Wlin[k * 32 + c]);
        else if (c < 64)  return __ldg(&Wfilm[k * 64 + (c - 32)]);
        else if (c < 96)  return __ldg(&Wfilm[k * 64 + 32 + (c - 64)]);
        else if (c < 128) return __ldg(&Wls[k * 32 + (c - 96)]);
        else if (c < 160) return __ldg(&Wfs[k * 64 + (c - 128)]);
        else              return __ldg(&Wfs[k * 64 + 32 + (c - 160)]);
    };
    auto getB = [&](int c) -> float {
        if (c < 32)      return 0.0f;
        else if (c < 96) return __ldg(&bfilm[c - 32]);
        else             return 0.0f;
    };

    // B fragments: b0 = W[k0+tq][n], b1 = W[k0+tq+4][n], n = n0+g
    u32 bfr[6][4][2];
    float acc[6][4];
#pragma unroll
    for (int nt = 0; nt < 6; nt++) {
        int n0 = warp * 48 + nt * 8;
        int n = n0 + g;
#pragma unroll
        for (int ks = 0; ks < 4; ks++) {
            int k0 = 8 * ks;
            bfr[nt][ks][0] = f2tf32(getW(k0 + tq, n));
            bfr[nt][ks][1] = f2tf32(getW(k0 + tq + 4, n));
        }
        float b0 = getB(n0 + 2 * tq);
        float b1 = getB(n0 + 2 * tq + 1);
        acc[nt][0] = b0; acc[nt][1] = b1; acc[nt][2] = b0; acc[nt][3] = b1;
    }

    // --- Stage h = relu(A + S) as tf32 words ---
    {
        int m = tid >> 3;
        int f0 = (tid & 7) << 2;
        int node = i0 + m;
        float4 a = make_float4(0, 0, 0, 0), s = make_float4(0, 0, 0, 0);
        if (node < N) {
            a = *(const float4*)&g_bufA[node * DD + f0];
            s = *(const float4*)&g_bufS[node * DD + f0];
        }
        sh_h[m][f0 + 0] = f2tf32(fmaxf(a.x + s.x, 0.0f));
        sh_h[m][f0 + 1] = f2tf32(fmaxf(a.y + s.y, 0.0f));
        sh_h[m][f0 + 2] = f2tf32(fmaxf(a.z + s.z, 0.0f));
        sh_h[m][f0 + 3] = f2tf32(fmaxf(a.w + s.w, 0.0f));
    }
    __syncthreads();

    // --- MMA: 4 k-steps x 6 n-tiles ---
#pragma unroll
    for (int ks = 0; ks < 4; ks++) {
        int k0 = 8 * ks;
        u32 a0 = sh_h[g][k0 + tq];
        u32 a1 = sh_h[g + 8][k0 + tq];
        u32 a2 = sh_h[g][k0 + tq + 4];
        u32 a3 = sh_h[g + 8][k0 + tq + 4];
#pragma unroll
        for (int nt = 0; nt < 6; nt++) {
            mma_tf32(acc[nt][0], acc[nt][1], acc[nt][2], acc[nt][3],
                     a0, a1, a2, a3, bfr[nt][ks][0], bfr[nt][ks][1],
                     acc[nt][0], acc[nt][1], acc[nt][2], acc[nt][3]);
        }
    }

    // --- Scatter accumulators to smem ---
#pragma unroll
    for (int nt = 0; nt < 6; nt++) {
        int c = warp * 48 + nt * 8 + 2 * tq;
        sout[g][c] = acc[nt][0];
        sout[g][c + 1] = acc[nt][1];
        sout[g + 8][c] = acc[nt][2];
        sout[g + 8][c + 1] = acc[nt][3];
    }
    __syncthreads();

    // --- Epilogue ---
    {
        int m = tid >> 3;
        int f0 = (tid & 7) << 2;
        int node = i0 + m;
        if (node < N) {
            float4 xl = *(const float4*)&sout[m][f0];
            float4 be = *(const float4*)&sout[m][32 + f0];
            float4 ga = *(const float4*)&sout[m][64 + f0];
            float4 ls = *(const float4*)&sout[m][96 + f0];
            float4 bs = *(const float4*)&sout[m][128 + f0];
            float4 gs = *(const float4*)&sout[m][160 + f0];
            int t = node * DD + f0;
            *reinterpret_cast<uint2*>(&g_bQ[t]) =
                make_uint2(pack_bf2(xl.x, xl.y), pack_bf2(xl.z, xl.w));
            *reinterpret_cast<uint2*>(&g_bK[t]) =
                make_uint2(pack_bf2(be.x, be.y), pack_bf2(be.z, be.w));
            *reinterpret_cast<uint2*>(&g_bV[t]) =
                make_uint2(pack_bf2(ga.x, ga.y), pack_bf2(ga.z, ga.w));
            float4 h;
            h.x = fmaxf(fmaf(gs.x, ls.x, bs.x), 0.0f);
            h.y = fmaxf(fmaf(gs.y, ls.y, bs.y), 0.0f);
            h.z = fmaxf(fmaf(gs.z, ls.z, bs.z), 0.0f);
            h.w = fmaxf(fmaf(gs.w, ls.w, bs.w), 0.0f);
            *(float4*)&g_bufH[t] = h;
        }
    }
}

// ---------------------------------------------------------------------------
// Layer-3 node transform via tensor cores (tf32).
// Fused W [32 x 128]: warp w handles matrix w (Wk/Wq/Wv/Ws), 4 n-tiles.
// Input h2 = relu(fma(A, 1/max(deg,1), H)).
__global__ __launch_bounds__(128) void node3_mma_kernel(
    int N,
    const float* __restrict__ Wk, const float* __restrict__ bk,
    const float* __restrict__ Wq, const float* __restrict__ bq,
    const float* __restrict__ Wv, const float* __restrict__ bv,
    const float* __restrict__ Ws, const float* __restrict__ b)
{
    __shared__ u32 sh_h[16][33];
    __shared__ float sout[16][136];

    int tid = threadIdx.x;
    int lane = tid & 31;
    int warp = tid >> 5;
    int g = lane >> 2;
    int tq = lane & 3;
    int i0 = blockIdx.x * 16;

    const float* Wsel = (warp == 0) ? Wk : (warp == 1) ? Wq : (warp == 2) ? Wv : Ws;
    const float* bsel = (warp == 0) ? bk : (warp == 1) ? bq : (warp == 2) ? bv : b;

    u32 bfr[4][4][2];
    float acc[4][4];
#pragma unroll
    for (int nt = 0; nt < 4; nt++) {
        int nc = nt * 8 + g;
#pragma unroll
        for (int ks = 0; ks < 4; ks++) {
            int k0 = 8 * ks;
            bfr[nt][ks][0] = f2tf32(__ldg(&Wsel[(k0 + tq) * 32 + nc]));
            bfr[nt][ks][1] = f2tf32(__ldg(&Wsel[(k0 + tq + 4) * 32 + nc]));
        }
        float b0 = __ldg(&bsel[nt * 8 + 2 * tq]);
        float b1 = __ldg(&bsel[nt * 8 + 2 * tq + 1]);
        acc[nt][0] = b0; acc[nt][1] = b1; acc[nt][2] = b0; acc[nt][3] = b1;
    }

    // --- Stage h2 = relu(fma(A, 1/max(deg,1), H)) as tf32 ---
    {
        int m = tid >> 3;
        int f0 = (tid & 7) << 2;
        int node = i0 + m;
        float4 a = make_float4(0, 0, 0, 0), hh = make_float4(0, 0, 0, 0);
        float inv = 1.0f;
        if (node < N) {
            inv = __frcp_rn(fmaxf(__ldg(&g_deg[node]), 1.0f));
            a = *(const float4*)&g_bufA[node * DD + f0];
            hh = *(const float4*)&g_bufH[node * DD + f0];
        }
        sh_h[m][f0 + 0] = f2tf32(fmaxf(fmaf(a.x, inv, hh.x), 0.0f));
        sh_h[m][f0 + 1] = f2tf32(fmaxf(fmaf(a.y, inv, hh.y), 0.0f));
        sh_h[m][f0 + 2] = f2tf32(fmaxf(fmaf(a.z, inv, hh.z), 0.0f));
        sh_h[m][f0 + 3] = f2tf32(fmaxf(fmaf(a.w, inv, hh.w), 0.0f));
    }
    __syncthreads();

#pragma unroll
    for (int ks = 0; ks < 4; ks++) {
        int k0 = 8 * ks;
        u32 a0 = sh_h[g][k0 + tq];
        u32 a1 = sh_h[g + 8][k0 + tq];
        u32 a2 = sh_h[g][k0 + tq + 4];
        u32 a3 = sh_h[g + 8][k0 + tq + 4];
#pragma unroll
        for (int nt = 0; nt < 4; nt++) {
            mma_tf32(acc[nt][0], acc[nt][1], acc[nt][2], acc[nt][3],
                     a0, a1, a2, a3, bfr[nt][ks][0], bfr[nt][ks][1],
                     acc[nt][0], acc[nt][1], acc[nt][2], acc[nt][3]);
        }
    }

#pragma unroll
    for (int nt = 0; nt < 4; nt++) {
        int c = warp * 32 + nt * 8 + 2 * tq;
        sout[g][c] = acc[nt][0];
        sout[g][c + 1] = acc[nt][1];
        sout[g + 8][c] = acc[nt][2];
        sout[g + 8][c + 1] = acc[nt][3];
    }
    __syncthreads();

    // --- Epilogue: K,Q,V -> bf16; S -> fp32 ---
    {
        int m = tid >> 3;
        int f0 = (tid & 7) << 2;
        int node = i0 + m;
        if (node < N) {
            float4 kk = *(const float4*)&sout[m][f0];
            float4 qq = *(const float4*)&sout[m][32 + f0];
            float4 vv = *(const float4*)&sout[m][64 + f0];
            float4 ss = *(const float4*)&sout[m][96 + f0];
            int t = node * DD + f0;
            *reinterpret_cast<uint2*>(&g_bK[t]) =
                make_uint2(pack_bf2(kk.x, kk.y), pack_bf2(kk.z, kk.w));
            *reinterpret_cast<uint2*>(&g_bQ[t]) =
                make_uint2(pack_bf2(qq.x, qq.y), pack_bf2(qq.z, qq.w));
            *reinterpret_cast<uint2*>(&g_bV[t]) =
                make_uint2(pack_bf2(vv.x, vv.y), pack_bf2(vv.z, vv.w));
            *(float4*)&g_bufS[t] = ss;
        }
    }
}

// ---------------------------------------------------------------------------
// Pool: h3 = agg + skip; gsum[batch[i]] += h3, 8 lanes per node
__global__ __launch_bounds__(256) void pool_kernel(
    const int* __restrict__ batch, int N)
{
    int gt = blockIdx.x * blockDim.x + threadIdx.x;
    int i = gt >> 3;
    if (i >= N) return;
    int c = (gt & 7) << 2;
    int t = i * DD + c;
    float4 a = *(const float4*)&g_bufA[t];
    float4 s = *(const float4*)&g_bufS[t];
    float4 r;
    r.x = a.x + s.x; r.y = a.y + s.y; r.z = a.z + s.z; r.w = a.w + s.w;
    int bgr = __ldg(&batch[i]);
    red_add_v4(&g_gsum[bgr * DD + c], r);
    if ((gt & 7) == 0) atomicAdd(&g_gcnt[bgr], 1.0f);
}

// ---------------------------------------------------------------------------
__global__ __launch_bounds__(128) void final_kernel(
    const float* __restrict__ linW, const float* __restrict__ linb,
    float* __restrict__ out, int G)
{
    __shared__ float sW[DD * CC];
    __shared__ float sb[CC];
    for (int j = threadIdx.x; j < DD * CC; j += blockDim.x) sW[j] = linW[j];
    if (threadIdx.x < CC) sb[threadIdx.x] = linb[threadIdx.x];
    __syncthreads();

    int g = blockIdx.x * blockDim.x + threadIdx.x;
    if (g >= G) return;
    float inv = __frcp_rn(fmaxf(g_gcnt[g], 1.0f));
    float acc[CC];
#pragma unroll
    for (int c = 0; c < CC; c++) acc[c] = sb[c];
#pragma unroll
    for (int j = 0; j < DD; j++) {
        float m = g_gsum[g * DD + j] * inv;
#pragma unroll
        for (int c = 0; c < CC; c++) acc[c] = fmaf(m, sW[j * CC + c], acc[c]);
    }
#pragma unroll
    for (int c = 0; c < CC; c++) out[g * CC + c] = acc[c];
}

// ---------------------------------------------------------------------------
static inline int nblk(long long threads, int tpb) {
    return (int)((threads + tpb - 1) / tpb);
}

extern "C" void kernel_launch(void* const* d_in, const int* in_sizes, int n_in,
                              void* d_out, int out_size)
{
    const float* x     = (const float*)d_in[0];
    const int*   ei    = (const int*)d_in[1];
    const int*   batch = (const int*)d_in[2];
    const float* c1_Wk = (const float*)d_in[4];
    const float* c1_bk = (const float*)d_in[5];
    const float* c1_Wq = (const float*)d_in[6];
    const float* c1_bq = (const float*)d_in[7];
    const float* c1_Wv = (const float*)d_in[8];
    const float* c1_bv = (const float*)d_in[9];
    const float* c1_Ws = (const float*)d_in[10];
    const float* c1_b  = (const float*)d_in[11];
    const float* c2_Wlin  = (const float*)d_in[12];
    const float* c2_Wfilm = (const float*)d_in[13];
    const float* c2_bfilm = (const float*)d_in[14];
    const float* c2_Wls   = (const float*)d_in[15];
    const float* c2_Wfs   = (const float*)d_in[16];
    const float* c3_Wk = (const float*)d_in[17];
    const float* c3_bk = (const float*)d_in[18];
    const float* c3_Wq = (const float*)d_in[19];
    const float* c3_bq = (const float*)d_in[20];
    const float* c3_Wv = (const float*)d_in[21];
    const float* c3_bv = (const float*)d_in[22];
    const float* c3_Ws = (const float*)d_in[23];
    const float* c3_b  = (const float*)d_in[24];
    const float* linW  = (const float*)d_in[25];
    const float* linb  = (const float*)d_in[26];
    float* out = (float*)d_out;

    int N = in_sizes[0];
    int E = in_sizes[1] / 2;
    int G = out_size / CC;

    void *pA, *pDeg, *pGs, *pGc;
    cudaGetSymbolAddress(&pA,   g_bufA);
    cudaGetSymbolAddress(&pDeg, g_deg);
    cudaGetSymbolAddress(&pGs,  g_gsum);
    cudaGetSymbolAddress(&pGc,  g_gcnt);

    const int TPB = 256;
    long long NT = (long long)N * DD;
    long long E8 = (long long)E * 8;
    long long N8 = (long long)N * 8;
    int TILES = (N + 15) / 16;

    // ---- Layer 1: ResGated(1 -> 32) ----
    node1_kernel<<<nblk(NT, TPB), TPB>>>(x, N, c1_Wk, c1_bk, c1_Wq, c1_bq,
                                         c1_Wv, c1_bv, c1_Ws, c1_b);
    cudaMemsetAsync(pA, 0, (size_t)NT * sizeof(float));
    cudaMemsetAsync(pDeg, 0, (size_t)N * sizeof(float));
    edge_resgated_kernel<<<nblk(E8, TPB), TPB>>>(ei, E, 1);

    // ---- Layer 2: FiLM(32 -> 32) node transform on tensor cores (tf32) ----
    film_mma_kernel<<<TILES, 128>>>(N, c2_Wlin, c2_Wfilm, c2_bfilm,
                                    c2_Wls, c2_Wfs);
    cudaMemsetAsync(pA, 0, (size_t)NT * sizeof(float));
    edge_film_kernel<<<nblk(E8, TPB), TPB>>>(ei, E);

    // ---- Layer 3: ResGated(32 -> 32) node transform on tensor cores ----
    node3_mma_kernel<<<TILES, 128>>>(N, c3_Wk, c3_bk, c3_Wq, c3_bq,
                                     c3_Wv, c3_bv, c3_Ws, c3_b);
    cudaMemsetAsync(pA, 0, (size_t)NT * sizeof(float));
    edge_resgated_kernel<<<nblk(E8, TPB), TPB>>>(ei, E, 0);

    // ---- Global mean pool + classifier ----
    cudaMemsetAsync(pGs, 0, (size_t)G * DD * sizeof(float));
    cudaMemsetAsync(pGc, 0, (size_t)G * sizeof(float));
    pool_kernel<<<nblk(N8, TPB), TPB>>>(batch, N);
    final_kernel<<<nblk(G, 128), 128>>>(linW, linb, out, G);
}

// round 12
// speedup vs baseline: 2.6030x; 1.0331x over previous
#include <cuda_runtime.h>
#include <cuda_bf16.h>
#include <math.h>

// Problem constants: N=100000, E=1600000, G=1024, D=32, C=10
#define DD 32
#define CC 10
#define MAX_N 100352
#define MAX_G 2048

typedef unsigned long long u64;
typedef unsigned int u32;

// Scratch (alloc-free rule: __device__ globals)
// g_pair: per-node interleaved pair operand, 64 bf16 = 8 chunks of 16B.
//   chunk c (features 4c..4c+3): {first[4c..4c+3], second[4c..4c+3]}
//   resgated layers: (q, v) gathered from src
//   film layer:      (beta, gamma) gathered from dst
// g_single: per-node single operand, 32 bf16 (k for resgated, xl for film)
__device__ __align__(16) __nv_bfloat16 g_pair[MAX_N * 2 * DD];
__device__ __align__(16) __nv_bfloat16 g_single[MAX_N * DD];
__device__ float g_bufS[MAX_N * DD];   // skip path (fp32)
__device__ float g_bufH[MAX_N * DD];   // film skip output (fp32)
__device__ float g_bufA[MAX_N * DD];   // aggregation target (fp32)
__device__ float g_deg[MAX_N];
__device__ float g_gsum[MAX_G * DD];
__device__ float g_gcnt[MAX_G];

// ---------------------------------------------------------------------------
__device__ __forceinline__ void red_add_v4(float* addr, float4 v) {
    asm volatile("red.global.add.v4.f32 [%0], {%1,%2,%3,%4};"
                 :: "l"(addr), "f"(v.x), "f"(v.y), "f"(v.z), "f"(v.w)
                 : "memory");
}
__device__ __forceinline__ float sigmoidf_fast(float x) {
    return __frcp_rn(1.0f + __expf(-x));
}
__device__ __forceinline__ float2 bf2f(u32 w) {
    __nv_bfloat162 h = *reinterpret_cast<__nv_bfloat162*>(&w);
    return __bfloat1622float2(h);
}
// Load 4 consecutive bf16 (8B) and widen to float4.
__device__ __forceinline__ float4 ld_bf4(const __nv_bfloat16* base, int idx4) {
    uint2 r = __ldg(((const uint2*)base) + idx4);
    float2 fa = bf2f(r.x), fb = bf2f(r.y);
    return make_float4(fa.x, fa.y, fb.x, fb.y);
}
__device__ __forceinline__ u32 pack_bf2(float lo, float hi) {
    __nv_bfloat162 h = __floats2bfloat162_rn(lo, hi);
    return *reinterpret_cast<u32*>(&h);
}
__device__ __forceinline__ u32 f2tf32(float f) {
    u32 r;
    asm("cvt.rna.tf32.f32 %0, %1;" : "=r"(r) : "f"(f));
    return r;
}
// mma.sync m16n8k8 row.col f32.tf32.tf32.f32
__device__ __forceinline__ void mma_tf32(
    float& d0, float& d1, float& d2, float& d3,
    u32 a0, u32 a1, u32 a2, u32 a3, u32 b0, u32 b1,
    float c0, float c1, float c2, float c3)
{
    asm volatile(
        "mma.sync.aligned.m16n8k8.row.col.f32.tf32.tf32.f32 "
        "{%0,%1,%2,%3}, {%4,%5,%6,%7}, {%8,%9}, {%10,%11,%12,%13};"
        : "=f"(d0), "=f"(d1), "=f"(d2), "=f"(d3)
        : "r"(a0), "r"(a1), "r"(a2), "r"(a3), "r"(b0), "r"(b1),
          "f"(c0), "f"(c1), "f"(c2), "f"(c3));
}

// ---------------------------------------------------------------------------
// Layer 1 node transform (F_IN = 1): single=k, pair=(q,v), S fp32
__global__ __launch_bounds__(256) void node1_kernel(
    const float* __restrict__ x, int N,
    const float* __restrict__ Wk, const float* __restrict__ bk,
    const float* __restrict__ Wq, const float* __restrict__ bq,
    const float* __restrict__ Wv, const float* __restrict__ bv,
    const float* __restrict__ Ws, const float* __restrict__ b)
{
    int t = blockIdx.x * blockDim.x + threadIdx.x;
    if (t >= N * DD) return;
    int i = t >> 5;
    int d = t & 31;
    float xv = __ldg(&x[i]);
    float k = fmaf(xv, __ldg(&Wk[d]), __ldg(&bk[d]));
    float q = fmaf(xv, __ldg(&Wq[d]), __ldg(&bq[d]));
    float v = fmaf(xv, __ldg(&Wv[d]), __ldg(&bv[d]));
    g_single[t] = __float2bfloat16(k);
    int pbase = i * 64 + (d >> 2) * 8 + (d & 3);
    g_pair[pbase]     = __float2bfloat16(q);
    g_pair[pbase + 4] = __float2bfloat16(v);
    g_bufS[t] = fmaf(xv, __ldg(&Ws[d]), __ldg(&b[d]));
}

// ---------------------------------------------------------------------------
// ResGated edge pass: 8 lanes/edge; k from single[dst] (LDG.64),
// (q,v) from pair[src] (LDG.128), fp32 vector reduction.
__global__ __launch_bounds__(256) void edge_resgated_kernel(
    const int* __restrict__ ei, int E, int count_deg)
{
    int gt = blockIdx.x * blockDim.x + threadIdx.x;
    int e = gt >> 3;
    if (e >= E) return;
    int c = gt & 7;
    int s = __ldg(&ei[e]);
    int d = __ldg(&ei[E + e]);
    float4 k = ld_bf4(g_single, d * 8 + c);
    uint4 r = __ldg(((const uint4*)g_pair) + s * 8 + c);
    float2 q01 = bf2f(r.x), q23 = bf2f(r.y);
    float2 v01 = bf2f(r.z), v23 = bf2f(r.w);
    float4 m;
    m.x = sigmoidf_fast(k.x + q01.x) * v01.x;
    m.y = sigmoidf_fast(k.y + q01.y) * v01.y;
    m.z = sigmoidf_fast(k.z + q23.x) * v23.x;
    m.w = sigmoidf_fast(k.w + q23.y) * v23.y;
    red_add_v4(&g_bufA[d * DD + (c << 2)], m);
    if (count_deg && c == 0) atomicAdd(&g_deg[d], 1.0f);
}

// ---------------------------------------------------------------------------
// FiLM edge pass: (beta,gamma) from pair[dst] (LDG.128),
// xl from single[src] (LDG.64): agg[dst] += relu(gamma*xl + beta)
__global__ __launch_bounds__(256) void edge_film_kernel(
    const int* __restrict__ ei, int E)
{
    int gt = blockIdx.x * blockDim.x + threadIdx.x;
    int e = gt >> 3;
    if (e >= E) return;
    int c = gt & 7;
    int s = __ldg(&ei[e]);
    int d = __ldg(&ei[E + e]);
    uint4 r = __ldg(((const uint4*)g_pair) + d * 8 + c);
    float2 b01 = bf2f(r.x), b23 = bf2f(r.y);
    float2 g01 = bf2f(r.z), g23 = bf2f(r.w);
    float4 xl = ld_bf4(g_single, s * 8 + c);
    float4 m;
    m.x = fmaxf(fmaf(g01.x, xl.x, b01.x), 0.0f);
    m.y = fmaxf(fmaf(g01.y, xl.y, b01.y), 0.0f);
    m.z = fmaxf(fmaf(g23.x, xl.z, b23.x), 0.0f);
    m.w = fmaxf(fmaf(g23.y, xl.w, b23.y), 0.0f);
    red_add_v4(&g_bufA[d * DD + (c << 2)], m);
}

// ---------------------------------------------------------------------------
// FiLM node transform via tensor cores (tf32, m16n8k8, 4 k-steps).
// Fused output matrix W_all [32 x 192]:
//   cols 0-31: Wlin | 32-63: film beta(+b) | 64-95: film gamma(+b)
//   96-127: Wls | 128-159: fs beta | 160-191: fs gamma
// Epilogue: single=xl, pair=(beta,gamma), H fp32.
__global__ __launch_bounds__(128) void film_mma_kernel(
    int N,
    const float* __restrict__ Wlin, const float* __restrict__ Wfilm,
    const float* __restrict__ bfilm,
    const float* __restrict__ Wls, const float* __restrict__ Wfs)
{
    __shared__ u32 sh_h[16][33];              // h tile as tf32 words, padded
    __shared__ float sout[16][200];           // 192 cols + pad

    int tid = threadIdx.x;
    int lane = tid & 31;
    int warp = tid >> 5;
    int g = lane >> 2;      // 0..7
    int tq = lane & 3;      // 0..3
    int i0 = blockIdx.x * 16;

    auto getW = [&](int k, int c) -> float {
        if (c < 32)       return __ldg(&Wlin[k * 32 + c]);
        else if (c < 64)  return __ldg(&Wfilm[k * 64 + (c - 32)]);
        else if (c < 96)  return __ldg(&Wfilm[k * 64 + 32 + (c - 64)]);
        else if (c < 128) return __ldg(&Wls[k * 32 + (c - 96)]);
        else if (c < 160) return __ldg(&Wfs[k * 64 + (c - 128)]);
        else              return __ldg(&Wfs[k * 64 + 32 + (c - 160)]);
    };
    auto getB = [&](int c) -> float {
        if (c < 32)      return 0.0f;
        else if (c < 96) return __ldg(&bfilm[c - 32]);
        else             return 0.0f;
    };

    u32 bfr[6][4][2];
    float acc[6][4];
#pragma unroll
    for (int nt = 0; nt < 6; nt++) {
        int n0 = warp * 48 + nt * 8;
        int n = n0 + g;
#pragma unroll
        for (int ks = 0; ks < 4; ks++) {
            int k0 = 8 * ks;
            bfr[nt][ks][0] = f2tf32(getW(k0 + tq, n));
            bfr[nt][ks][1] = f2tf32(getW(k0 + tq + 4, n));
        }
        float b0 = getB(n0 + 2 * tq);
        float b1 = getB(n0 + 2 * tq + 1);
        acc[nt][0] = b0; acc[nt][1] = b1; acc[nt][2] = b0; acc[nt][3] = b1;
    }

    // --- Stage h = relu(A + S) as tf32 words ---
    {
        int m = tid >> 3;
        int f0 = (tid & 7) << 2;
        int node = i0 + m;
        float4 a = make_float4(0, 0, 0, 0), s = make_float4(0, 0, 0, 0);
        if (node < N) {
            a = *(const float4*)&g_bufA[node * DD + f0];
            s = *(const float4*)&g_bufS[node * DD + f0];
        }
        sh_h[m][f0 + 0] = f2tf32(fmaxf(a.x + s.x, 0.0f));
        sh_h[m][f0 + 1] = f2tf32(fmaxf(a.y + s.y, 0.0f));
        sh_h[m][f0 + 2] = f2tf32(fmaxf(a.z + s.z, 0.0f));
        sh_h[m][f0 + 3] = f2tf32(fmaxf(a.w + s.w, 0.0f));
    }
    __syncthreads();

    // --- MMA: 4 k-steps x 6 n-tiles ---
#pragma unroll
    for (int ks = 0; ks < 4; ks++) {
        int k0 = 8 * ks;
        u32 a0 = sh_h[g][k0 + tq];
        u32 a1 = sh_h[g + 8][k0 + tq];
        u32 a2 = sh_h[g][k0 + tq + 4];
        u32 a3 = sh_h[g + 8][k0 + tq + 4];
#pragma unroll
        for (int nt = 0; nt < 6; nt++) {
            mma_tf32(acc[nt][0], acc[nt][1], acc[nt][2], acc[nt][3],
                     a0, a1, a2, a3, bfr[nt][ks][0], bfr[nt][ks][1],
                     acc[nt][0], acc[nt][1], acc[nt][2], acc[nt][3]);
        }
    }

#pragma unroll
    for (int nt = 0; nt < 6; nt++) {
        int c = warp * 48 + nt * 8 + 2 * tq;
        sout[g][c] = acc[nt][0];
        sout[g][c + 1] = acc[nt][1];
        sout[g + 8][c] = acc[nt][2];
        sout[g + 8][c + 1] = acc[nt][3];
    }
    __syncthreads();

    // --- Epilogue ---
    {
        int m = tid >> 3;
        int f0 = (tid & 7) << 2;
        int node = i0 + m;
        if (node < N) {
            float4 xl = *(const float4*)&sout[m][f0];
            float4 be = *(const float4*)&sout[m][32 + f0];
            float4 ga = *(const float4*)&sout[m][64 + f0];
            float4 ls = *(const float4*)&sout[m][96 + f0];
            float4 bs = *(const float4*)&sout[m][128 + f0];
            float4 gs = *(const float4*)&sout[m][160 + f0];
            int t = node * DD + f0;
            *reinterpret_cast<uint2*>(&g_single[t]) =
                make_uint2(pack_bf2(xl.x, xl.y), pack_bf2(xl.z, xl.w));
            // pair chunk: {beta quad, gamma quad}
            uint4 pc = make_uint4(pack_bf2(be.x, be.y), pack_bf2(be.z, be.w),
                                  pack_bf2(ga.x, ga.y), pack_bf2(ga.z, ga.w));
            ((uint4*)g_pair)[node * 8 + (f0 >> 2)] = pc;
            float4 h;
            h.x = fmaxf(fmaf(gs.x, ls.x, bs.x), 0.0f);
            h.y = fmaxf(fmaf(gs.y, ls.y, bs.y), 0.0f);
            h.z = fmaxf(fmaf(gs.z, ls.z, bs.z), 0.0f);
            h.w = fmaxf(fmaf(gs.w, ls.w, bs.w), 0.0f);
            *(float4*)&g_bufH[t] = h;
        }
    }
}

// ---------------------------------------------------------------------------
// Layer-3 node transform via tensor cores (tf32).
// Warp w handles matrix w (Wk/Wq/Wv/Ws). Input h2 = relu(fma(A,1/deg,H)).
// Epilogue: single=k, pair=(q,v), S fp32.
__global__ __launch_bounds__(128) void node3_mma_kernel(
    int N,
    const float* __restrict__ Wk, const float* __restrict__ bk,
    const float* __restrict__ Wq, const float* __restrict__ bq,
    const float* __restrict__ Wv, const float* __restrict__ bv,
    const float* __restrict__ Ws, const float* __restrict__ b)
{
    __shared__ u32 sh_h[16][33];
    __shared__ float sout[16][136];

    int tid = threadIdx.x;
    int lane = tid & 31;
    int warp = tid >> 5;
    int g = lane >> 2;
    int tq = lane & 3;
    int i0 = blockIdx.x * 16;

    const float* Wsel = (warp == 0) ? Wk : (warp == 1) ? Wq : (warp == 2) ? Wv : Ws;
    const float* bsel = (warp == 0) ? bk : (warp == 1) ? bq : (warp == 2) ? bv : b;

    u32 bfr[4][4][2];
    float acc[4][4];
#pragma unroll
    for (int nt = 0; nt < 4; nt++) {
        int nc = nt * 8 + g;
#pragma unroll
        for (int ks = 0; ks < 4; ks++) {
            int k0 = 8 * ks;
            bfr[nt][ks][0] = f2tf32(__ldg(&Wsel[(k0 + tq) * 32 + nc]));
            bfr[nt][ks][1] = f2tf32(__ldg(&Wsel[(k0 + tq + 4) * 32 + nc]));
        }
        float b0 = __ldg(&bsel[nt * 8 + 2 * tq]);
        float b1 = __ldg(&bsel[nt * 8 + 2 * tq + 1]);
        acc[nt][0] = b0; acc[nt][1] = b1; acc[nt][2] = b0; acc[nt][3] = b1;
    }

    // --- Stage h2 = relu(fma(A, 1/max(deg,1), H)) as tf32 ---
    {
        int m = tid >> 3;
        int f0 = (tid & 7) << 2;
        int node = i0 + m;
        float4 a = make_float4(0, 0, 0, 0), hh = make_float4(0, 0, 0, 0);
        float inv = 1.0f;
        if (node < N) {
            inv = __frcp_rn(fmaxf(__ldg(&g_deg[node]), 1.0f));
            a = *(const float4*)&g_bufA[node * DD + f0];
            hh = *(const float4*)&g_bufH[node * DD + f0];
        }
        sh_h[m][f0 + 0] = f2tf32(fmaxf(fmaf(a.x, inv, hh.x), 0.0f));
        sh_h[m][f0 + 1] = f2tf32(fmaxf(fmaf(a.y, inv, hh.y), 0.0f));
        sh_h[m][f0 + 2] = f2tf32(fmaxf(fmaf(a.z, inv, hh.z), 0.0f));
        sh_h[m][f0 + 3] = f2tf32(fmaxf(fmaf(a.w, inv, hh.w), 0.0f));
    }
    __syncthreads();

#pragma unroll
    for (int ks = 0; ks < 4; ks++) {
        int k0 = 8 * ks;
        u32 a0 = sh_h[g][k0 + tq];
        u32 a1 = sh_h[g + 8][k0 + tq];
        u32 a2 = sh_h[g][k0 + tq + 4];
        u32 a3 = sh_h[g + 8][k0 + tq + 4];
#pragma unroll
        for (int nt = 0; nt < 4; nt++) {
            mma_tf32(acc[nt][0], acc[nt][1], acc[nt][2], acc[nt][3],
                     a0, a1, a2, a3, bfr[nt][ks][0], bfr[nt][ks][1],
                     acc[nt][0], acc[nt][1], acc[nt][2], acc[nt][3]);
        }
    }

#pragma unroll
    for (int nt = 0; nt < 4; nt++) {
        int c = warp * 32 + nt * 8 + 2 * tq;
        sout[g][c] = acc[nt][0];
        sout[g][c + 1] = acc[nt][1];
        sout[g + 8][c] = acc[nt][2];
        sout[g + 8][c + 1] = acc[nt][3];
    }
    __syncthreads();

    // --- Epilogue: single=k, pair=(q,v), S fp32 ---
    {
        int m = tid >> 3;
        int f0 = (tid & 7) << 2;
        int node = i0 + m;
        if (node < N) {
            float4 kk = *(const float4*)&sout[m][f0];
            float4 qq = *(const float4*)&sout[m][32 + f0];
            float4 vv = *(const float4*)&sout[m][64 + f0];
            float4 ss = *(const float4*)&sout[m][96 + f0];
            int t = node * DD + f0;
            *reinterpret_cast<uint2*>(&g_single[t]) =
                make_uint2(pack_bf2(kk.x, kk.y), pack_bf2(kk.z, kk.w));
            uint4 pc = make_uint4(pack_bf2(qq.x, qq.y), pack_bf2(qq.z, qq.w),
                                  pack_bf2(vv.x, vv.y), pack_bf2(vv.z, vv.w));
            ((uint4*)g_pair)[node * 8 + (f0 >> 2)] = pc;
            *(float4*)&g_bufS[t] = ss;
        }
    }
}

// ---------------------------------------------------------------------------
// Pool: h3 = agg + skip; gsum[batch[i]] += h3, 8 lanes per node
__global__ __launch_bounds__(256) void pool_kernel(
    const int* __restrict__ batch, int N)
{
    int gt = blockIdx.x * blockDim.x + threadIdx.x;
    int i = gt >> 3;
    if (i >= N) return;
    int c = (gt & 7) << 2;
    int t = i * DD + c;
    float4 a = *(const float4*)&g_bufA[t];
    float4 s = *(const float4*)&g_bufS[t];
    float4 r;
    r.x = a.x + s.x; r.y = a.y + s.y; r.z = a.z + s.z; r.w = a.w + s.w;
    int bgr = __ldg(&batch[i]);
    red_add_v4(&g_gsum[bgr * DD + c], r);
    if ((gt & 7) == 0) atomicAdd(&g_gcnt[bgr], 1.0f);
}

// ---------------------------------------------------------------------------
__global__ __launch_bounds__(128) void final_kernel(
    const float* __restrict__ linW, const float* __restrict__ linb,
    float* __restrict__ out, int G)
{
    __shared__ float sW[DD * CC];
    __shared__ float sb[CC];
    for (int j = threadIdx.x; j < DD * CC; j += blockDim.x) sW[j] = linW[j];
    if (threadIdx.x < CC) sb[threadIdx.x] = linb[threadIdx.x];
    __syncthreads();

    int g = blockIdx.x * blockDim.x + threadIdx.x;
    if (g >= G) return;
    float inv = __frcp_rn(fmaxf(g_gcnt[g], 1.0f));
    float acc[CC];
#pragma unroll
    for (int c = 0; c < CC; c++) acc[c] = sb[c];
#pragma unroll
    for (int j = 0; j < DD; j++) {
        float m = g_gsum[g * DD + j] * inv;
#pragma unroll
        for (int c = 0; c < CC; c++) acc[c] = fmaf(m, sW[j * CC + c], acc[c]);
    }
#pragma unroll
    for (int c = 0; c < CC; c++) out[g * CC + c] = acc[c];
}

// ---------------------------------------------------------------------------
static inline int nblk(long long threads, int tpb) {
    return (int)((threads + tpb - 1) / tpb);
}

extern "C" void kernel_launch(void* const* d_in, const int* in_sizes, int n_in,
                              void* d_out, int out_size)
{
    const float* x     = (const float*)d_in[0];
    const int*   ei    = (const int*)d_in[1];
    const int*   batch = (const int*)d_in[2];
    const float* c1_Wk = (const float*)d_in[4];
    const float* c1_bk = (const float*)d_in[5];
    const float* c1_Wq = (const float*)d_in[6];
    const float* c1_bq = (const float*)d_in[7];
    const float* c1_Wv = (const float*)d_in[8];
    const float* c1_bv = (const float*)d_in[9];
    const float* c1_Ws = (const float*)d_in[10];
    const float* c1_b  = (const float*)d_in[11];
    const float* c2_Wlin  = (const float*)d_in[12];
    const float* c2_Wfilm = (const float*)d_in[13];
    const float* c2_bfilm = (const float*)d_in[14];
    const float* c2_Wls   = (const float*)d_in[15];
    const float* c2_Wfs   = (const float*)d_in[16];
    const float* c3_Wk = (const float*)d_in[17];
    const float* c3_bk = (const float*)d_in[18];
    const float* c3_Wq = (const float*)d_in[19];
    const float* c3_bq = (const float*)d_in[20];
    const float* c3_Wv = (const float*)d_in[21];
    const float* c3_bv = (const float*)d_in[22];
    const float* c3_Ws = (const float*)d_in[23];
    const float* c3_b  = (const float*)d_in[24];
    const float* linW  = (const float*)d_in[25];
    const float* linb  = (const float*)d_in[26];
    float* out = (float*)d_out;

    int N = in_sizes[0];
    int E = in_sizes[1] / 2;
    int G = out_size / CC;

    void *pA, *pDeg, *pGs, *pGc;
    cudaGetSymbolAddress(&pA,   g_bufA);
    cudaGetSymbolAddress(&pDeg, g_deg);
    cudaGetSymbolAddress(&pGs,  g_gsum);
    cudaGetSymbolAddress(&pGc,  g_gcnt);

    const int TPB = 256;
    long long NT = (long long)N * DD;
    long long E8 = (long long)E * 8;
    long long N8 = (long long)N * 8;
    int TILES = (N + 15) / 16;

    // ---- Layer 1: ResGated(1 -> 32) ----
    node1_kernel<<<nblk(NT, TPB), TPB>>>(x, N, c1_Wk, c1_bk, c1_Wq, c1_bq,
                                         c1_Wv, c1_bv, c1_Ws, c1_b);
    cudaMemsetAsync(pA, 0, (size_t)NT * sizeof(float));
    cudaMemsetAsync(pDeg, 0, (size_t)N * sizeof(float));
    edge_resgated_kernel<<<nblk(E8, TPB), TPB>>>(ei, E, 1);

    // ---- Layer 2: FiLM(32 -> 32) node transform on tensor cores (tf32) ----
    film_mma_kernel<<<TILES, 128>>>(N, c2_Wlin, c2_Wfilm, c2_bfilm,
                                    c2_Wls, c2_Wfs);
    cudaMemsetAsync(pA, 0, (size_t)NT * sizeof(float));
    edge_film_kernel<<<nblk(E8, TPB), TPB>>>(ei, E);

    // ---- Layer 3: ResGated(32 -> 32) node transform on tensor cores ----
    node3_mma_kernel<<<TILES, 128>>>(N, c3_Wk, c3_bk, c3_Wq, c3_bq,
                                     c3_Wv, c3_bv, c3_Ws, c3_b);
    cudaMemsetAsync(pA, 0, (size_t)NT * sizeof(float));
    edge_resgated_kernel<<<nblk(E8, TPB), TPB>>>(ei, E, 0);

    // ---- Global mean pool + classifier ----
    cudaMemsetAsync(pGs, 0, (size_t)G * DD * sizeof(float));
    cudaMemsetAsync(pGc, 0, (size_t)G * sizeof(float));
    pool_kernel<<<nblk(N8, TPB), TPB>>>(batch, N);
    final_kernel<<<nblk(G, 128), 128>>>(linW, linb, out, G);
}